// round 1
// baseline (speedup 1.0000x reference)
#include <cuda_runtime.h>
#include <math.h>

#define Bb 4
#define Ss 1024
#define Tt 1024
#define Dd 1024
#define Hh 16
#define DHh 2048
#define SP 1032   // S + 2*4 padding rows for conv1

// ---------------- scratch (device globals; no allocation allowed) ----------
__device__ float g_h [Bb*Ss*Dd];
__device__ float g_q [Bb*Ss*Dd];
__device__ float g_k [Bb*Tt*Dd];
__device__ float g_v [Bb*Tt*Dd];
__device__ float g_ao[Bb*Ss*Dd];
__device__ float g_x1[Bb*Ss*Dd];
__device__ float g_x2[Bb*Ss*Dd];
__device__ float g_z [Bb*Ss*Dd];
__device__ float g_xp[Bb*SP*Dd];
__device__ float g_y [(size_t)Bb*Ss*DHh];
__device__ float g_wp[(size_t)9*DHh*Dd];
__device__ float g_attn[(size_t)Bb*Hh*Ss*Tt];   // fallback if attn maps not in d_out

// ---------------- LayerNorm: one block per row of D=1024 -------------------
__global__ void ln_kernel(const float* __restrict__ x,
                          const float* __restrict__ gg,
                          const float* __restrict__ bb,
                          float* __restrict__ out)
{
    __shared__ float s1[8], s2[8], mv[2];
    long row = blockIdx.x;
    int t = threadIdx.x;
    float4 v = ((const float4*)(x + row * Dd))[t];
    float s = v.x + v.y + v.z + v.w;
    float q = v.x*v.x + v.y*v.y + v.z*v.z + v.w*v.w;
    #pragma unroll
    for (int o = 16; o > 0; o >>= 1) {
        s += __shfl_down_sync(0xffffffffu, s, o);
        q += __shfl_down_sync(0xffffffffu, q, o);
    }
    if ((t & 31) == 0) { s1[t >> 5] = s; s2[t >> 5] = q; }
    __syncthreads();
    if (t == 0) {
        float a = 0.f, c = 0.f;
        #pragma unroll
        for (int i = 0; i < 8; i++) { a += s1[i]; c += s2[i]; }
        float mu  = a * (1.0f / Dd);
        float var = c * (1.0f / Dd) - mu * mu;
        mv[0] = mu; mv[1] = rsqrtf(var + 1e-5f);
    }
    __syncthreads();
    float mu = mv[0], rs = mv[1];
    float4 gv = ((const float4*)gg)[t];
    float4 bv = ((const float4*)bb)[t];
    float4 o;
    o.x = (v.x - mu) * rs * gv.x + bv.x;
    o.y = (v.y - mu) * rs * gv.y + bv.y;
    o.z = (v.z - mu) * rs * gv.z + bv.z;
    o.w = (v.w - mu) * rs * gv.w + bv.w;
    ((float4*)(out + row * Dd))[t] = o;
}

// ---------------- Softmax over rows of length T=1024 (in place) ------------
__global__ void softmax_kernel(float* __restrict__ w)
{
    __shared__ float s1[8];
    __shared__ float red[2];
    long row = blockIdx.x;
    int t = threadIdx.x;
    float4* rp = (float4*)(w + row * (long)Tt);
    float4 v = rp[t];
    float m = fmaxf(fmaxf(v.x, v.y), fmaxf(v.z, v.w));
    #pragma unroll
    for (int o = 16; o > 0; o >>= 1) m = fmaxf(m, __shfl_xor_sync(0xffffffffu, m, o));
    if ((t & 31) == 0) s1[t >> 5] = m;
    __syncthreads();
    if (t == 0) {
        float mm = s1[0];
        #pragma unroll
        for (int i = 1; i < 8; i++) mm = fmaxf(mm, s1[i]);
        red[0] = mm;
    }
    __syncthreads();
    float M = red[0];
    v.x = __expf(v.x - M); v.y = __expf(v.y - M);
    v.z = __expf(v.z - M); v.w = __expf(v.w - M);
    float s = v.x + v.y + v.z + v.w;
    #pragma unroll
    for (int o = 16; o > 0; o >>= 1) s += __shfl_xor_sync(0xffffffffu, s, o);
    __syncthreads();                 // protect s1 reuse
    if ((t & 31) == 0) s1[t >> 5] = s;
    __syncthreads();
    if (t == 0) {
        float ss = 0.f;
        #pragma unroll
        for (int i = 0; i < 8; i++) ss += s1[i];
        red[1] = 1.0f / ss;
    }
    __syncthreads();
    float inv = red[1];
    v.x *= inv; v.y *= inv; v.z *= inv; v.w *= inv;
    rp[t] = v;
}

// ---------------- Generic NT GEMM: C = (A @ B^T + bias)*alpha (+res)(relu) -
// 128x128 tile, BK=8, 256 threads, 8x8 per thread. Optional z-batching with
// two-level offsets (batch, head) for attention scores.
__global__ void __launch_bounds__(256)
gemm_nt(const float* __restrict__ A, int lda, long sAb, long sAh,
        const float* __restrict__ Bm, int ldb, long sBb, long sBh,
        float* __restrict__ C, int ldc, long sCb, long sCh,
        int K, int Hdiv,
        const float* __restrict__ bias,
        const float* __restrict__ res,
        float alpha, int relu)
{
    int z = blockIdx.z;
    int zb = z / Hdiv, zh = z - zb * Hdiv;
    A  += zb * sAb + zh * sAh;
    Bm += zb * sBb + zh * sBh;
    long coff = zb * sCb + zh * sCh;
    C += coff;
    if (res) res += coff;

    __shared__ float As[8][128];
    __shared__ float Bs[8][128];
    int t = threadIdx.x;
    int m0 = blockIdx.y * 128, n0 = blockIdx.x * 128;
    int lrow = t >> 1, lk = (t & 1) << 2;
    const float* Ap = A  + (long)(m0 + lrow) * lda + lk;
    const float* Bp = Bm + (long)(n0 + lrow) * ldb + lk;
    int tx = t & 15, ty = t >> 4;

    float acc[8][8];
    #pragma unroll
    for (int i = 0; i < 8; i++)
        #pragma unroll
        for (int j = 0; j < 8; j++) acc[i][j] = 0.f;

    for (int k0 = 0; k0 < K; k0 += 8) {
        float4 av = *(const float4*)(Ap + k0);
        float4 bv = *(const float4*)(Bp + k0);
        __syncthreads();
        As[lk + 0][lrow] = av.x; As[lk + 1][lrow] = av.y;
        As[lk + 2][lrow] = av.z; As[lk + 3][lrow] = av.w;
        Bs[lk + 0][lrow] = bv.x; Bs[lk + 1][lrow] = bv.y;
        Bs[lk + 2][lrow] = bv.z; Bs[lk + 3][lrow] = bv.w;
        __syncthreads();
        #pragma unroll
        for (int kk = 0; kk < 8; kk++) {
            float ar[8], br[8];
            *(float4*)&ar[0] = *(const float4*)&As[kk][ty * 8];
            *(float4*)&ar[4] = *(const float4*)&As[kk][ty * 8 + 4];
            *(float4*)&br[0] = *(const float4*)&Bs[kk][tx * 8];
            *(float4*)&br[4] = *(const float4*)&Bs[kk][tx * 8 + 4];
            #pragma unroll
            for (int i = 0; i < 8; i++)
                #pragma unroll
                for (int j = 0; j < 8; j++)
                    acc[i][j] += ar[i] * br[j];
        }
    }

    float bl[8];
    #pragma unroll
    for (int j = 0; j < 8; j++) bl[j] = bias ? bias[n0 + tx * 8 + j] : 0.f;

    #pragma unroll
    for (int i = 0; i < 8; i++) {
        long crow = m0 + ty * 8 + i;
        float* cp = C + crow * ldc + n0 + tx * 8;
        float o[8];
        #pragma unroll
        for (int j = 0; j < 8; j++) o[j] = (acc[i][j] + bl[j]) * alpha;
        if (res) {
            const float* rp2 = res + crow * ldc + n0 + tx * 8;
            float4 r0 = *(const float4*)rp2, r1 = *(const float4*)(rp2 + 4);
            o[0]+=r0.x; o[1]+=r0.y; o[2]+=r0.z; o[3]+=r0.w;
            o[4]+=r1.x; o[5]+=r1.y; o[6]+=r1.z; o[7]+=r1.w;
        }
        if (relu) {
            #pragma unroll
            for (int j = 0; j < 8; j++) o[j] = fmaxf(o[j], 0.f);
        }
        *(float4*)cp       = make_float4(o[0], o[1], o[2], o[3]);
        *(float4*)(cp + 4) = make_float4(o[4], o[5], o[6], o[7]);
    }
}

// ---------------- W @ V per (b,h): NN GEMM, M=1024, N=64, K=1024 -----------
__global__ void __launch_bounds__(256)
gemm_av(const float* __restrict__ W, const float* __restrict__ V,
        float* __restrict__ C)
{
    int z = blockIdx.z;
    int zb = z >> 4, zh = z & 15;
    W += (long)z * Ss * Tt;
    V += (long)zb * Tt * Dd + zh * 64;
    C += (long)zb * Ss * Dd + zh * 64;

    __shared__ float As[16][128];
    __shared__ float Bs[16][64];
    int t = threadIdx.x;
    int m0 = blockIdx.y * 128;
    int ar = t >> 2, asg = (t & 3) << 2;
    const float* Ap0 = W + (long)(m0 + ar) * Tt + asg;
    const float* Ap1 = W + (long)(m0 + ar + 64) * Tt + asg;
    int bkr = t >> 4, bc = (t & 15) << 2;
    const float* Bp = V + (long)bkr * Dd + bc;
    int tx = t & 15, ty = t >> 4;

    float acc[8][4];
    #pragma unroll
    for (int i = 0; i < 8; i++)
        #pragma unroll
        for (int j = 0; j < 4; j++) acc[i][j] = 0.f;

    for (int k0 = 0; k0 < Tt; k0 += 16) {
        float4 a0 = *(const float4*)(Ap0 + k0);
        float4 a1 = *(const float4*)(Ap1 + k0);
        float4 bv = *(const float4*)(Bp + (long)k0 * Dd);
        __syncthreads();
        As[asg+0][ar]    = a0.x; As[asg+1][ar]    = a0.y;
        As[asg+2][ar]    = a0.z; As[asg+3][ar]    = a0.w;
        As[asg+0][ar+64] = a1.x; As[asg+1][ar+64] = a1.y;
        As[asg+2][ar+64] = a1.z; As[asg+3][ar+64] = a1.w;
        *(float4*)&Bs[bkr][bc] = bv;
        __syncthreads();
        #pragma unroll
        for (int kk = 0; kk < 16; kk++) {
            float arr[8];
            *(float4*)&arr[0] = *(const float4*)&As[kk][ty * 8];
            *(float4*)&arr[4] = *(const float4*)&As[kk][ty * 8 + 4];
            float4 b4 = *(const float4*)&Bs[kk][tx * 4];
            float brr[4] = {b4.x, b4.y, b4.z, b4.w};
            #pragma unroll
            for (int i = 0; i < 8; i++)
                #pragma unroll
                for (int j = 0; j < 4; j++)
                    acc[i][j] += arr[i] * brr[j];
        }
    }
    #pragma unroll
    for (int i = 0; i < 8; i++) {
        float* cp = C + (long)(m0 + ty * 8 + i) * Dd + tx * 4;
        *(float4*)cp = make_float4(acc[i][0], acc[i][1], acc[i][2], acc[i][3]);
    }
}

// ---------------- conv1 as GEMM over K = 9*1024 on padded input ------------
// A(m, kk) = xpad[b, s+kk/1024, kk%1024], B(n, kk) = wp[kk/1024, n, kk%1024]
__global__ void __launch_bounds__(256)
gemm_conv1(const float* __restrict__ xp, const float* __restrict__ Wp,
           float* __restrict__ C, const float* __restrict__ bias)
{
    __shared__ float As[8][128];
    __shared__ float Bs[8][128];
    int t = threadIdx.x;
    int m0 = blockIdx.y * 128, n0 = blockIdx.x * 128;
    int lrow = t >> 1, lk = (t & 1) << 2;
    int m = m0 + lrow;
    int mb = m >> 10, ms = m & 1023;
    const float* Ap  = xp + ((long)(mb * SP + ms)) * Dd + lk;
    const float* Bp0 = Wp + (long)(n0 + lrow) * Dd + lk;
    int tx = t & 15, ty = t >> 4;

    float acc[8][8];
    #pragma unroll
    for (int i = 0; i < 8; i++)
        #pragma unroll
        for (int j = 0; j < 8; j++) acc[i][j] = 0.f;

    for (int k0 = 0; k0 < 9 * Dd; k0 += 8) {
        int kc = k0 >> 10;
        int ci = k0 & 1023;
        float4 av = *(const float4*)(Ap  + (long)kc * Dd + ci);
        float4 bv = *(const float4*)(Bp0 + (long)kc * DHh * Dd + ci);
        __syncthreads();
        As[lk + 0][lrow] = av.x; As[lk + 1][lrow] = av.y;
        As[lk + 2][lrow] = av.z; As[lk + 3][lrow] = av.w;
        Bs[lk + 0][lrow] = bv.x; Bs[lk + 1][lrow] = bv.y;
        Bs[lk + 2][lrow] = bv.z; Bs[lk + 3][lrow] = bv.w;
        __syncthreads();
        #pragma unroll
        for (int kk = 0; kk < 8; kk++) {
            float ar8[8], br8[8];
            *(float4*)&ar8[0] = *(const float4*)&As[kk][ty * 8];
            *(float4*)&ar8[4] = *(const float4*)&As[kk][ty * 8 + 4];
            *(float4*)&br8[0] = *(const float4*)&Bs[kk][tx * 8];
            *(float4*)&br8[4] = *(const float4*)&Bs[kk][tx * 8 + 4];
            #pragma unroll
            for (int i = 0; i < 8; i++)
                #pragma unroll
                for (int j = 0; j < 8; j++)
                    acc[i][j] += ar8[i] * br8[j];
        }
    }

    float bl[8];
    #pragma unroll
    for (int j = 0; j < 8; j++) bl[j] = bias[n0 + tx * 8 + j];
    #pragma unroll
    for (int i = 0; i < 8; i++) {
        float* cp = C + (long)(m0 + ty * 8 + i) * DHh + n0 + tx * 8;
        float o[8];
        #pragma unroll
        for (int j = 0; j < 8; j++) o[j] = fmaxf(acc[i][j] + bl[j], 0.f);
        *(float4*)cp       = make_float4(o[0], o[1], o[2], o[3]);
        *(float4*)(cp + 4) = make_float4(o[4], o[5], o[6], o[7]);
    }
}

// ---------------- helpers: pad copy, weight repack --------------------------
__global__ void pad_kernel(const float* __restrict__ x, float* __restrict__ xp)
{
    long i = (long)blockIdx.x * 256 + threadIdx.x;   // over Bb*SP*Dd
    int c = (int)(i & 1023);
    long r = i >> 10;                                 // b*SP + row
    int b = (int)(r / SP);
    int s = (int)(r - (long)b * SP);
    float val = 0.f;
    if (s >= 4 && s < Ss + 4) val = x[((long)b * Ss + (s - 4)) * Dd + c];
    xp[i] = val;
}

__global__ void repack_kernel(const float* __restrict__ w, float* __restrict__ wp)
{
    long i = (long)blockIdx.x * 256 + threadIdx.x;   // over 9*DHh*Dd
    int ci = (int)(i & 1023);
    long r = i >> 10;                                 // k*DHh + co
    int k  = (int)(r >> 11);
    int co = (int)(r & 2047);
    wp[i] = w[((long)co * Dd + ci) * 9 + k];
}

// ---------------- launcher --------------------------------------------------
extern "C" void kernel_launch(void* const* d_in, const int* in_sizes, int n_in,
                              void* d_out, int out_size)
{
    const float* x    = (const float*)d_in[0];
    const float* xa   = (const float*)d_in[1];
    const float* Wq1  = (const float*)d_in[2];
    const float* bq1  = (const float*)d_in[3];
    const float* Wk1  = (const float*)d_in[4];
    const float* Wv1  = (const float*)d_in[5];
    const float* bv1  = (const float*)d_in[6];
    const float* Wo1  = (const float*)d_in[7];
    const float* bo1  = (const float*)d_in[8];
    const float* gln1 = (const float*)d_in[9];
    const float* bln1 = (const float*)d_in[10];
    const float* Wq2  = (const float*)d_in[11];
    const float* bq2  = (const float*)d_in[12];
    const float* Wk2  = (const float*)d_in[13];
    const float* Wv2  = (const float*)d_in[14];
    const float* bv2  = (const float*)d_in[15];
    const float* Wo2  = (const float*)d_in[16];
    const float* bo2  = (const float*)d_in[17];
    const float* gln2 = (const float*)d_in[18];
    const float* bln2 = (const float*)d_in[19];
    const float* wc1  = (const float*)d_in[20];
    const float* bc1  = (const float*)d_in[21];
    const float* wc2  = (const float*)d_in[22];
    const float* bc2  = (const float*)d_in[23];
    const float* gln3 = (const float*)d_in[24];
    const float* bln3 = (const float*)d_in[25];

    float *ph, *pq, *pk, *pv, *pao, *px1, *px2, *pz, *pxp, *py, *pwp, *pattn;
    cudaGetSymbolAddress((void**)&ph,   g_h);
    cudaGetSymbolAddress((void**)&pq,   g_q);
    cudaGetSymbolAddress((void**)&pk,   g_k);
    cudaGetSymbolAddress((void**)&pv,   g_v);
    cudaGetSymbolAddress((void**)&pao,  g_ao);
    cudaGetSymbolAddress((void**)&px1,  g_x1);
    cudaGetSymbolAddress((void**)&px2,  g_x2);
    cudaGetSymbolAddress((void**)&pz,   g_z);
    cudaGetSymbolAddress((void**)&pxp,  g_xp);
    cudaGetSymbolAddress((void**)&py,   g_y);
    cudaGetSymbolAddress((void**)&pwp,  g_wp);
    cudaGetSymbolAddress((void**)&pattn, g_attn);

    float* out = (float*)d_out;
    const size_t off1 = (size_t)Bb * Ss * Dd;
    const size_t asz  = (size_t)Bb * Hh * Ss * Tt;
    float* attn1 = pattn;
    float* attn2 = pattn;
    if ((size_t)out_size >= off1 + 2 * asz) {
        attn1 = out + off1;
        attn2 = out + off1 + asz;
    }

    const float scale = 0.35355339059327373f;   // 64^(-0.25)
    dim3 blk(256);
    dim3 gp(Dd / 128, (Bb * Ss) / 128, 1);
    dim3 gs(Tt / 128, Ss / 128, Bb * Hh);
    dim3 ga(1, Ss / 128, Bb * Hh);

    // ---- self attention ----
    ln_kernel<<<Bb * Ss, 256>>>(x, gln1, bln1, ph);
    gemm_nt<<<gp, blk>>>(ph, Dd, 0, 0, Wq1, Dd, 0, 0, pq, Dd, 0, 0, Dd, 1, bq1, nullptr, scale, 0);
    gemm_nt<<<gp, blk>>>(ph, Dd, 0, 0, Wk1, Dd, 0, 0, pk, Dd, 0, 0, Dd, 1, nullptr, nullptr, scale, 0);
    gemm_nt<<<gp, blk>>>(ph, Dd, 0, 0, Wv1, Dd, 0, 0, pv, Dd, 0, 0, Dd, 1, bv1, nullptr, 1.f, 0);
    gemm_nt<<<gs, blk>>>(pq, Dd, (long)Ss * Dd, 64,
                         pk, Dd, (long)Tt * Dd, 64,
                         attn1, Tt, (long)Hh * Ss * Tt, (long)Ss * Tt,
                         64, Hh, nullptr, nullptr, 1.f, 0);
    softmax_kernel<<<Bb * Hh * Ss, 256>>>(attn1);
    gemm_av<<<ga, blk>>>(attn1, pv, pao);
    gemm_nt<<<gp, blk>>>(pao, Dd, 0, 0, Wo1, Dd, 0, 0, px1, Dd, 0, 0, Dd, 1, bo1, x, 1.f, 0);

    // ---- cross attention ----
    ln_kernel<<<Bb * Ss, 256>>>(px1, gln2, bln2, ph);
    gemm_nt<<<gp, blk>>>(ph, Dd, 0, 0, Wq2, Dd, 0, 0, pq, Dd, 0, 0, Dd, 1, bq2, nullptr, scale, 0);
    gemm_nt<<<gp, blk>>>(xa, Dd, 0, 0, Wk2, Dd, 0, 0, pk, Dd, 0, 0, Dd, 1, nullptr, nullptr, scale, 0);
    gemm_nt<<<gp, blk>>>(xa, Dd, 0, 0, Wv2, Dd, 0, 0, pv, Dd, 0, 0, Dd, 1, bv2, nullptr, 1.f, 0);
    gemm_nt<<<gs, blk>>>(pq, Dd, (long)Ss * Dd, 64,
                         pk, Dd, (long)Tt * Dd, 64,
                         attn2, Tt, (long)Hh * Ss * Tt, (long)Ss * Tt,
                         64, Hh, nullptr, nullptr, 1.f, 0);
    softmax_kernel<<<Bb * Hh * Ss, 256>>>(attn2);
    gemm_av<<<ga, blk>>>(attn2, pv, pao);
    gemm_nt<<<gp, blk>>>(pao, Dd, 0, 0, Wo2, Dd, 0, 0, px2, Dd, 0, 0, Dd, 1, bo2, px1, 1.f, 0);

    // ---- conv FFN ----
    repack_kernel<<<(9 * DHh * Dd) / 256, 256>>>(wc1, pwp);
    pad_kernel<<<(Bb * SP * Dd) / 256, 256>>>(px2, pxp);
    dim3 gc1(DHh / 128, (Bb * Ss) / 128, 1);
    gemm_conv1<<<gc1, blk>>>(pxp, pwp, py, bc1);
    dim3 gc2(Dd / 128, (Bb * Ss) / 128, 1);
    gemm_nt<<<gc2, blk>>>(py, DHh, 0, 0, wc2, DHh, 0, 0, pz, Dd, 0, 0, DHh, 1, bc2, px2, 1.f, 0);
    ln_kernel<<<Bb * Ss, 256>>>(pz, gln3, bln3, out);
}

// round 3
// speedup vs baseline: 4.1529x; 4.1529x over previous
#include <cuda_runtime.h>
#include <cuda_fp16.h>
#include <cstdint>
#include <math.h>

#define Bb 4
#define Ss 1024
#define Tt 1024
#define Dd 1024
#define Hh 16
#define DHh 2048
#define SP 1032   // S + 8 padding rows for conv1

// ======================= scratch ============================================
__device__ __half g16_h   [(size_t)Bb*Ss*Dd];
__device__ __half g16_q   [(size_t)Bb*Ss*Dd];
__device__ __half g16_k   [(size_t)Bb*Tt*Dd];
__device__ __half g16_v   [(size_t)Bb*Tt*Dd];
__device__ __half g16_vt  [(size_t)Bb*Hh*64*Tt];
__device__ __half g16_ao  [(size_t)Bb*Ss*Dd];
__device__ __half g16_xa  [(size_t)Bb*Tt*Dd];
__device__ __half g16_attn[(size_t)Bb*Hh*Ss*Tt];
__device__ __half g16_xpad[(size_t)Bb*SP*Dd];
__device__ __half g16_y   [(size_t)Bb*Ss*DHh];
__device__ __half g16_wp  [(size_t)8*Dd*Dd];
__device__ __half g16_wc1 [(size_t)DHh*9*Dd];
__device__ __half g16_wc2 [(size_t)Dd*DHh];
__device__ float  g_x1 [Bb*Ss*Dd];
__device__ float  g_x2 [Bb*Ss*Dd];
__device__ float  g_z  [Bb*Ss*Dd];
__device__ float  g_attn[(size_t)Bb*Hh*Ss*Tt];   // fallback if attn not in d_out

// ======================= small PTX helpers ==================================
__device__ __forceinline__ void cpa16(void* s, const void* g) {
    uint32_t sa = (uint32_t)__cvta_generic_to_shared(s);
    asm volatile("cp.async.cg.shared.global [%0], [%1], 16;"
                 :: "r"(sa), "l"(__cvta_generic_to_global(g)));
}
#define CP_COMMIT() asm volatile("cp.async.commit_group;" ::: "memory")
#define CP_WAIT1()  asm volatile("cp.async.wait_group 1;" ::: "memory")
#define CP_WAIT0()  asm volatile("cp.async.wait_group 0;" ::: "memory")

__device__ __forceinline__ void ldmx4(uint32_t* r, const void* p) {
    uint32_t a = (uint32_t)__cvta_generic_to_shared(p);
    asm volatile("ldmatrix.sync.aligned.m8n8.x4.shared.b16 {%0,%1,%2,%3}, [%4];"
                 : "=r"(r[0]), "=r"(r[1]), "=r"(r[2]), "=r"(r[3]) : "r"(a));
}
__device__ __forceinline__ void mma16816(float* c, const uint32_t* a, const uint32_t* b) {
    asm volatile("mma.sync.aligned.m16n8k16.row.col.f32.f16.f16.f32 "
                 "{%0,%1,%2,%3}, {%4,%5,%6,%7}, {%8,%9}, {%0,%1,%2,%3};"
                 : "+f"(c[0]), "+f"(c[1]), "+f"(c[2]), "+f"(c[3])
                 : "r"(a[0]), "r"(a[1]), "r"(a[2]), "r"(a[3]),
                   "r"(b[0]), "r"(b[1]));
}

// ======================= LayerNorm ==========================================
template<bool OUTH>
__global__ void ln_kernel(const float* __restrict__ x,
                          const float* __restrict__ gg,
                          const float* __restrict__ bb,
                          void* __restrict__ outv)
{
    __shared__ float s1[8], s2[8], mv[2];
    long row = blockIdx.x;
    int t = threadIdx.x;
    float4 v = ((const float4*)(x + row * Dd))[t];
    float s = v.x + v.y + v.z + v.w;
    float q = v.x*v.x + v.y*v.y + v.z*v.z + v.w*v.w;
    #pragma unroll
    for (int o = 16; o > 0; o >>= 1) {
        s += __shfl_down_sync(0xffffffffu, s, o);
        q += __shfl_down_sync(0xffffffffu, q, o);
    }
    if ((t & 31) == 0) { s1[t >> 5] = s; s2[t >> 5] = q; }
    __syncthreads();
    if (t == 0) {
        float a = 0.f, c = 0.f;
        #pragma unroll
        for (int i = 0; i < 8; i++) { a += s1[i]; c += s2[i]; }
        float mu  = a * (1.0f / Dd);
        float var = c * (1.0f / Dd) - mu * mu;
        mv[0] = mu; mv[1] = rsqrtf(var + 1e-5f);
    }
    __syncthreads();
    float mu = mv[0], rs = mv[1];
    float4 gv = ((const float4*)gg)[t];
    float4 bv = ((const float4*)bb)[t];
    float o0 = (v.x - mu) * rs * gv.x + bv.x;
    float o1 = (v.y - mu) * rs * gv.y + bv.y;
    float o2 = (v.z - mu) * rs * gv.z + bv.z;
    float o3 = (v.w - mu) * rs * gv.w + bv.w;
    if (OUTH) {
        __align__(8) __half hh[4] = {__float2half(o0), __float2half(o1),
                                     __float2half(o2), __float2half(o3)};
        *(uint2*)((__half*)outv + row * Dd + t * 4) = *(uint2*)hh;
    } else {
        ((float4*)((float*)outv + row * Dd))[t] = make_float4(o0, o1, o2, o3);
    }
}

// ======================= Softmax (fp32 in place + fp16 copy) ================
__global__ void softmax_kernel(float* __restrict__ w, __half* __restrict__ w16)
{
    __shared__ float s1[8];
    __shared__ float red[2];
    long row = blockIdx.x;
    int t = threadIdx.x;
    float4* rp = (float4*)(w + row * (long)Tt);
    float4 v = rp[t];
    float m = fmaxf(fmaxf(v.x, v.y), fmaxf(v.z, v.w));
    #pragma unroll
    for (int o = 16; o > 0; o >>= 1) m = fmaxf(m, __shfl_xor_sync(0xffffffffu, m, o));
    if ((t & 31) == 0) s1[t >> 5] = m;
    __syncthreads();
    if (t == 0) {
        float mm = s1[0];
        #pragma unroll
        for (int i = 1; i < 8; i++) mm = fmaxf(mm, s1[i]);
        red[0] = mm;
    }
    __syncthreads();
    float M = red[0];
    v.x = __expf(v.x - M); v.y = __expf(v.y - M);
    v.z = __expf(v.z - M); v.w = __expf(v.w - M);
    float s = v.x + v.y + v.z + v.w;
    #pragma unroll
    for (int o = 16; o > 0; o >>= 1) s += __shfl_xor_sync(0xffffffffu, s, o);
    __syncthreads();
    if ((t & 31) == 0) s1[t >> 5] = s;
    __syncthreads();
    if (t == 0) {
        float ss = 0.f;
        #pragma unroll
        for (int i = 0; i < 8; i++) ss += s1[i];
        red[1] = 1.0f / ss;
    }
    __syncthreads();
    float inv = red[1];
    v.x *= inv; v.y *= inv; v.z *= inv; v.w *= inv;
    rp[t] = v;
    __align__(8) __half hh[4] = {__float2half(v.x), __float2half(v.y),
                                 __float2half(v.z), __float2half(v.w)};
    *(uint2*)(w16 + row * (long)Tt + t * 4) = *(uint2*)hh;
}

// ======================= HMMA fp16 GEMM (NT) ================================
// C[128 x BN] per CTA. A [M,K] row-major fp16, B [N,K] row-major fp16.
// C = (A@B^T + bias)*alpha (+res)(relu); out fp16 or fp32.
template<int BN, bool CONV, bool OUTH>
__global__ void __launch_bounds__(256)
gemm_mma(const __half* __restrict__ A, int lda, long sAb, long sAh,
         const __half* __restrict__ B, int ldb, long sBb, long sBh,
         void* __restrict__ Cv, int ldc, long sCb, long sCh,
         int K, int Hdiv,
         const float* __restrict__ bias,
         const float* __restrict__ res,
         float alpha, int relu)
{
    constexpr int WGM = (BN == 128) ? 2 : 4;     // warps along M
    constexpr int WM  = 128 / WGM;               // 64 or 32
    constexpr int WN  = BN / (8 / WGM);          // 32
    constexpr int MFR = WM / 16;                 // 4 or 2
    constexpr int NFR = WN / 8;                  // 4

    __shared__ __align__(16) __half As[2][128][40];
    __shared__ __align__(16) __half Bs[2][BN][40];

    const int t = threadIdx.x;
    const int lane = t & 31;
    const int w = t >> 5;
    const int wm = (w % WGM) * WM;
    const int wn = (w / WGM) * WN;

    int z = blockIdx.z;
    int zb = z / Hdiv, zh = z - zb * Hdiv;
    A += zb * sAb + zh * sAh;
    B += zb * sBb + zh * sBh;
    const long coff = zb * sCb + zh * sCh;
    const int m0 = blockIdx.y * 128, n0 = blockIdx.x * BN;

    // per-thread global load coords
    const int ar = t >> 1, ac = (t & 1) * 16;   // A: 2 chunks of 8 halves
    long abase = 0;
    const __half* agA = A;
    if (CONV) { int m = m0 + ar; abase = (long)((m >> 10) * SP + (m & 1023)); }
    else        agA = A + (long)(m0 + ar) * lda;

    const int br = (BN == 128) ? (t >> 1) : (t >> 2);
    const int bc = (BN == 128) ? ((t & 1) * 16) : ((t & 3) * 8);
    const __half* bg = B + (long)(n0 + br) * ldb;

    float acc[MFR][NFR][4];
    #pragma unroll
    for (int i = 0; i < MFR; i++)
        #pragma unroll
        for (int j = 0; j < NFR; j++)
            #pragma unroll
            for (int q = 0; q < 4; q++) acc[i][j][q] = 0.f;

    const int KC = K >> 5;   // BK = 32

    // ---- loader ----
    auto loadbuf = [&](int buf, int k0) {
        if (CONV) {
            int kk = k0 + ac;
            int kc = kk >> 10, ci = kk & 1023;
            const __half* gp = A + (abase + kc) * (long)Dd + ci;
            cpa16(&As[buf][ar][ac],     gp);
            cpa16(&As[buf][ar][ac + 8], gp + 8);
        } else {
            const __half* gp = agA + k0 + ac;
            cpa16(&As[buf][ar][ac],     gp);
            cpa16(&As[buf][ar][ac + 8], gp + 8);
        }
        if (BN == 128) {
            const __half* gp = bg + k0 + bc;
            cpa16(&Bs[buf][br][bc],     gp);
            cpa16(&Bs[buf][br][bc + 8], gp + 8);
        } else {
            const __half* gp = bg + k0 + bc;
            cpa16(&Bs[buf][br][bc], gp);
        }
    };

    loadbuf(0, 0);
    CP_COMMIT();
    int buf = 0;

    const int lr16 = lane & 15;
    const int lk8  = (lane >> 4) * 8;

    for (int c = 0; c < KC; ++c) {
        if (c + 1 < KC) {
            loadbuf(buf ^ 1, (c + 1) * 32);
            CP_COMMIT();
            CP_WAIT1();
        } else {
            CP_WAIT0();
        }
        __syncthreads();

        #pragma unroll
        for (int ks = 0; ks < 32; ks += 16) {
            uint32_t a[MFR][4];
            #pragma unroll
            for (int mf = 0; mf < MFR; mf++)
                ldmx4(a[mf], &As[buf][wm + mf * 16 + lr16][ks + lk8]);
            uint32_t bf[NFR][2];
            #pragma unroll
            for (int p = 0; p < NFR / 2; p++) {
                uint32_t mrr[4];
                ldmx4(mrr, &Bs[buf][wn + p * 16 + lr16][ks + lk8]);
                bf[2*p][0]   = mrr[0]; bf[2*p][1]   = mrr[2];
                bf[2*p+1][0] = mrr[1]; bf[2*p+1][1] = mrr[3];
            }
            #pragma unroll
            for (int mf = 0; mf < MFR; mf++)
                #pragma unroll
                for (int nf = 0; nf < NFR; nf++)
                    mma16816(acc[mf][nf], a[mf], bf[nf]);
        }
        __syncthreads();
        buf ^= 1;
    }

    // ---- epilogue ----
    const int lr = lane >> 2;
    const int lc = (lane & 3) * 2;
    #pragma unroll
    for (int mf = 0; mf < MFR; mf++) {
        #pragma unroll
        for (int i = 0; i < 2; i++) {
            long mrow = m0 + wm + mf * 16 + lr + i * 8;
            #pragma unroll
            for (int nf = 0; nf < NFR; nf++) {
                int col = n0 + wn + nf * 8 + lc;
                float v0 = acc[mf][nf][i * 2 + 0];
                float v1 = acc[mf][nf][i * 2 + 1];
                if (bias) { v0 += bias[col]; v1 += bias[col + 1]; }
                v0 *= alpha; v1 *= alpha;
                if (res) {
                    float2 rv = *(const float2*)(res + coff + mrow * ldc + col);
                    v0 += rv.x; v1 += rv.y;
                }
                if (relu) { v0 = fmaxf(v0, 0.f); v1 = fmaxf(v1, 0.f); }
                if (OUTH) {
                    __half2 hv = __floats2half2_rn(v0, v1);
                    *(__half2*)((__half*)Cv + coff + mrow * ldc + col) = hv;
                } else {
                    *(float2*)((float*)Cv + coff + mrow * ldc + col) = make_float2(v0, v1);
                }
            }
        }
    }
}

// ======================= prep kernels =======================================
__global__ void cast16(const float* __restrict__ s, __half* __restrict__ d, long n)
{
    long i = ((long)blockIdx.x * 256 + threadIdx.x) * 8;
    if (i >= n) return;
    float4 a = *(const float4*)(s + i);
    float4 b = *(const float4*)(s + i + 4);
    __align__(16) __half h[8] = {
        __float2half(a.x), __float2half(a.y), __float2half(a.z), __float2half(a.w),
        __float2half(b.x), __float2half(b.y), __float2half(b.z), __float2half(b.w)};
    *(uint4*)(d + i) = *(uint4*)h;
}

__global__ void pad_cast(const float* __restrict__ x, __half* __restrict__ xp)
{
    long i = (long)blockIdx.x * 256 + threadIdx.x;   // over Bb*SP*Dd
    int c = (int)(i & 1023);
    long r = i >> 10;
    int b = (int)(r / SP);
    int s = (int)(r - (long)b * SP);
    float val = 0.f;
    if (s >= 4 && s < Ss + 4) val = x[((long)b * Ss + (s - 4)) * Dd + c];
    xp[i] = __float2half(val);
}

__global__ void repack16(const float* __restrict__ w, __half* __restrict__ wp)
{
    long i = (long)blockIdx.x * 256 + threadIdx.x;   // over DHh*9216
    int kk = (int)(i % 9216);
    long n = i / 9216;
    int kc = kk >> 10, ci = kk & 1023;
    wp[i] = __float2half(w[(n * Dd + ci) * 9 + kc]);
}

// vt[b,h,n,t] = v16[b,t,h*64+n]
__global__ void transpose_v(const __half* __restrict__ v, __half* __restrict__ vt)
{
    __shared__ __half s[64][72];
    int tc = blockIdx.x, h = blockIdx.y, b = blockIdx.z;
    int t = threadIdx.x;
    int r = t >> 2;
    int c = (t & 3) * 16;
    const __half* src = v + ((long)b * Tt + tc * 64 + r) * Dd + h * 64 + c;
    *(uint4*)&s[r][c]     = *(const uint4*)src;
    *(uint4*)&s[r][c + 8] = *(const uint4*)(src + 8);
    __syncthreads();
    int n = t >> 2;
    int ts = (t & 3) * 16;
    __align__(16) __half o[16];
    #pragma unroll
    for (int j = 0; j < 16; j++) o[j] = s[ts + j][n];
    __half* dst = vt + ((long)((b * Hh + h) * 64 + n)) * Tt + tc * 64 + ts;
    *(uint4*)dst       = *(uint4*)&o[0];
    *(uint4*)(dst + 8) = *(uint4*)&o[8];
}

// ======================= launcher ===========================================
extern "C" void kernel_launch(void* const* d_in, const int* in_sizes, int n_in,
                              void* d_out, int out_size)
{
    const float* x    = (const float*)d_in[0];
    const float* xa   = (const float*)d_in[1];
    const float* Wq1  = (const float*)d_in[2];
    const float* bq1  = (const float*)d_in[3];
    const float* Wk1  = (const float*)d_in[4];
    const float* Wv1  = (const float*)d_in[5];
    const float* bv1  = (const float*)d_in[6];
    const float* Wo1  = (const float*)d_in[7];
    const float* bo1  = (const float*)d_in[8];
    const float* gln1 = (const float*)d_in[9];
    const float* bln1 = (const float*)d_in[10];
    const float* Wq2  = (const float*)d_in[11];
    const float* bq2  = (const float*)d_in[12];
    const float* Wk2  = (const float*)d_in[13];
    const float* Wv2  = (const float*)d_in[14];
    const float* bv2  = (const float*)d_in[15];
    const float* Wo2  = (const float*)d_in[16];
    const float* bo2  = (const float*)d_in[17];
    const float* gln2 = (const float*)d_in[18];
    const float* bln2 = (const float*)d_in[19];
    const float* wc1  = (const float*)d_in[20];
    const float* bc1  = (const float*)d_in[21];
    const float* wc2  = (const float*)d_in[22];
    const float* bc2  = (const float*)d_in[23];
    const float* gln3 = (const float*)d_in[24];
    const float* bln3 = (const float*)d_in[25];

    __half *h16, *q16, *k16, *v16, *vt16, *ao16, *xa16, *at16, *xp16, *y16, *wp16, *wc116, *wc216;
    float *px1, *px2, *pz, *pattn;
    cudaGetSymbolAddress((void**)&h16,   g16_h);
    cudaGetSymbolAddress((void**)&q16,   g16_q);
    cudaGetSymbolAddress((void**)&k16,   g16_k);
    cudaGetSymbolAddress((void**)&v16,   g16_v);
    cudaGetSymbolAddress((void**)&vt16,  g16_vt);
    cudaGetSymbolAddress((void**)&ao16,  g16_ao);
    cudaGetSymbolAddress((void**)&xa16,  g16_xa);
    cudaGetSymbolAddress((void**)&at16,  g16_attn);
    cudaGetSymbolAddress((void**)&xp16,  g16_xpad);
    cudaGetSymbolAddress((void**)&y16,   g16_y);
    cudaGetSymbolAddress((void**)&wp16,  g16_wp);
    cudaGetSymbolAddress((void**)&wc116, g16_wc1);
    cudaGetSymbolAddress((void**)&wc216, g16_wc2);
    cudaGetSymbolAddress((void**)&px1,   g_x1);
    cudaGetSymbolAddress((void**)&px2,   g_x2);
    cudaGetSymbolAddress((void**)&pz,    g_z);
    cudaGetSymbolAddress((void**)&pattn, g_attn);

    float* out = (float*)d_out;
    const size_t off1 = (size_t)Bb * Ss * Dd;
    const size_t asz  = (size_t)Bb * Hh * Ss * Tt;
    float* attn1 = pattn;
    float* attn2 = pattn;
    if ((size_t)out_size >= off1 + 2 * asz) {
        attn1 = out + off1;
        attn2 = out + off1 + asz;
    }

    const float scale = 0.35355339059327373f;   // 64^(-0.25)
    const long MM = (long)1024 * 1024;
    dim3 blk(256);
    dim3 gproj(8, 32, 1);        // N=1024, M=4096
    dim3 gqk(8, 8, Bb * Hh);     // N=1024, M=1024 per (b,h)
    dim3 gav(1, 8, Bb * Hh);     // N=64,  M=1024 per (b,h)
    dim3 gc1(16, 32, 1);         // N=2048, M=4096
    dim3 gc2(8, 32, 1);          // N=1024, M=4096
    dim3 gtr(16, Hh, Bb);
    const long sAttnB = (long)Hh * Ss * Tt, sAttnH = (long)Ss * Tt;
    const long sQKb = (long)Ss * Dd;

    // ---- weight / input casts ----
    int cg = (int)((MM / 8 + 255) / 256);
    cast16<<<cg, 256>>>(Wq1, wp16 + 0 * MM, MM);
    cast16<<<cg, 256>>>(Wk1, wp16 + 1 * MM, MM);
    cast16<<<cg, 256>>>(Wv1, wp16 + 2 * MM, MM);
    cast16<<<cg, 256>>>(Wo1, wp16 + 3 * MM, MM);
    cast16<<<cg, 256>>>(Wq2, wp16 + 4 * MM, MM);
    cast16<<<cg, 256>>>(Wk2, wp16 + 5 * MM, MM);
    cast16<<<cg, 256>>>(Wv2, wp16 + 6 * MM, MM);
    cast16<<<cg, 256>>>(Wo2, wp16 + 7 * MM, MM);
    cast16<<<(int)(((long)Dd * DHh / 8 + 255) / 256), 256>>>(wc2, wc216, (long)Dd * DHh);
    cast16<<<(int)(((long)Bb * Tt * Dd / 8 + 255) / 256), 256>>>(xa, xa16, (long)Bb * Tt * Dd);
    repack16<<<(int)(((long)DHh * 9216 + 255) / 256), 256>>>(wc1, wc116);

    // ---- self attention ----
    ln_kernel<true><<<Bb * Ss, 256>>>(x, gln1, bln1, h16);
    gemm_mma<128,false,true><<<gproj, blk>>>(h16, Dd,0,0, wp16+0*MM, Dd,0,0, q16, Dd,0,0, Dd,1, bq1, nullptr, scale, 0);
    gemm_mma<128,false,true><<<gproj, blk>>>(h16, Dd,0,0, wp16+1*MM, Dd,0,0, k16, Dd,0,0, Dd,1, nullptr, nullptr, scale, 0);
    gemm_mma<128,false,true><<<gproj, blk>>>(h16, Dd,0,0, wp16+2*MM, Dd,0,0, v16, Dd,0,0, Dd,1, bv1, nullptr, 1.f, 0);
    transpose_v<<<gtr, 256>>>(v16, vt16);
    gemm_mma<128,false,false><<<gqk, blk>>>(q16, Dd, sQKb, 64, k16, Dd, sQKb, 64,
        attn1, Tt, sAttnB, sAttnH, 64, Hh, nullptr, nullptr, 1.f, 0);
    softmax_kernel<<<Bb * Hh * Ss, 256>>>(attn1, at16);
    gemm_mma<64,false,true><<<gav, blk>>>(at16, Tt, sAttnB, sAttnH,
        vt16, Tt, (long)Hh * 64 * Tt, (long)64 * Tt,
        ao16, Dd, (long)Ss * Dd, 64, Tt, Hh, nullptr, nullptr, 1.f, 0);
    gemm_mma<128,false,false><<<gproj, blk>>>(ao16, Dd,0,0, wp16+3*MM, Dd,0,0, px1, Dd,0,0, Dd,1, bo1, x, 1.f, 0);

    // ---- cross attention ----
    ln_kernel<true><<<Bb * Ss, 256>>>(px1, gln2, bln2, h16);
    gemm_mma<128,false,true><<<gproj, blk>>>(h16, Dd,0,0, wp16+4*MM, Dd,0,0, q16, Dd,0,0, Dd,1, bq2, nullptr, scale, 0);
    gemm_mma<128,false,true><<<gproj, blk>>>(xa16, Dd,0,0, wp16+5*MM, Dd,0,0, k16, Dd,0,0, Dd,1, nullptr, nullptr, scale, 0);
    gemm_mma<128,false,true><<<gproj, blk>>>(xa16, Dd,0,0, wp16+6*MM, Dd,0,0, v16, Dd,0,0, Dd,1, bv2, nullptr, 1.f, 0);
    transpose_v<<<gtr, 256>>>(v16, vt16);
    gemm_mma<128,false,false><<<gqk, blk>>>(q16, Dd, sQKb, 64, k16, Dd, sQKb, 64,
        attn2, Tt, sAttnB, sAttnH, 64, Hh, nullptr, nullptr, 1.f, 0);
    softmax_kernel<<<Bb * Hh * Ss, 256>>>(attn2, at16);
    gemm_mma<64,false,true><<<gav, blk>>>(at16, Tt, sAttnB, sAttnH,
        vt16, Tt, (long)Hh * 64 * Tt, (long)64 * Tt,
        ao16, Dd, (long)Ss * Dd, 64, Tt, Hh, nullptr, nullptr, 1.f, 0);
    gemm_mma<128,false,false><<<gproj, blk>>>(ao16, Dd,0,0, wp16+7*MM, Dd,0,0, px2, Dd,0,0, Dd,1, bo2, px1, 1.f, 0);

    // ---- conv FFN ----
    pad_cast<<<(Bb * SP * Dd) / 256, 256>>>(px2, xp16);
    gemm_mma<128,true,true><<<gc1, blk>>>(xp16, Dd,0,0, wc116, 9216,0,0,
        y16, DHh,0,0, 9216, 1, bc1, nullptr, 1.f, 1);
    gemm_mma<128,false,false><<<gc2, blk>>>(y16, DHh,0,0, wc216, DHh,0,0,
        pz, Dd,0,0, DHh, 1, bc2, px2, 1.f, 0);
    ln_kernel<false><<<Bb * Ss, 256>>>(pz, gln3, bln3, out);
}

// round 4
// speedup vs baseline: 4.7669x; 1.1479x over previous
#include <cuda_runtime.h>
#include <cuda_fp16.h>
#include <cstdint>
#include <math.h>

#define Bb 4
#define Ss 1024
#define Tt 1024
#define Dd 1024
#define Hh 16
#define DHh 2048
#define SP 1032   // S + 8 padding rows for conv1

// ======================= scratch ============================================
__device__ __half g16_h   [(size_t)Bb*Ss*Dd];
__device__ __half g16_q   [(size_t)Bb*Ss*Dd];
__device__ __half g16_k   [(size_t)Bb*Tt*Dd];
__device__ __half g16_v   [(size_t)Bb*Tt*Dd];
__device__ __half g16_vt  [(size_t)Bb*Hh*64*Tt];
__device__ __half g16_ao  [(size_t)Bb*Ss*Dd];
__device__ __half g16_xa  [(size_t)Bb*Tt*Dd];
__device__ __half g16_attn[(size_t)Bb*Hh*Ss*Tt];
__device__ __half g16_xpad[(size_t)Bb*SP*Dd];
__device__ __half g16_y   [(size_t)Bb*Ss*DHh];
__device__ __half g16_wp  [(size_t)8*Dd*Dd];
__device__ __half g16_wc1 [(size_t)DHh*9*Dd];
__device__ __half g16_wc2 [(size_t)Dd*DHh];
__device__ float  g_x1 [Bb*Ss*Dd];
__device__ float  g_x2 [Bb*Ss*Dd];
__device__ float  g_z  [Bb*Ss*Dd];
__device__ float  g_attn[(size_t)Bb*Hh*Ss*Tt];   // fallback if attn not in d_out

// ======================= small PTX helpers ==================================
__device__ __forceinline__ void cpa16(void* s, const void* g) {
    uint32_t sa = (uint32_t)__cvta_generic_to_shared(s);
    asm volatile("cp.async.cg.shared.global [%0], [%1], 16;"
                 :: "r"(sa), "l"(__cvta_generic_to_global(g)));
}
#define CP_COMMIT() asm volatile("cp.async.commit_group;" ::: "memory")
#define CP_WAIT2()  asm volatile("cp.async.wait_group 2;" ::: "memory")
#define CP_WAIT1()  asm volatile("cp.async.wait_group 1;" ::: "memory")

__device__ __forceinline__ void ldmx4(uint32_t* r, const void* p) {
    uint32_t a = (uint32_t)__cvta_generic_to_shared(p);
    asm volatile("ldmatrix.sync.aligned.m8n8.x4.shared.b16 {%0,%1,%2,%3}, [%4];"
                 : "=r"(r[0]), "=r"(r[1]), "=r"(r[2]), "=r"(r[3]) : "r"(a));
}
__device__ __forceinline__ void mma16816(float* c, const uint32_t* a, const uint32_t* b) {
    asm volatile("mma.sync.aligned.m16n8k16.row.col.f32.f16.f16.f32 "
                 "{%0,%1,%2,%3}, {%4,%5,%6,%7}, {%8,%9}, {%0,%1,%2,%3};"
                 : "+f"(c[0]), "+f"(c[1]), "+f"(c[2]), "+f"(c[3])
                 : "r"(a[0]), "r"(a[1]), "r"(a[2]), "r"(a[3]),
                   "r"(b[0]), "r"(b[1]));
}

// ======================= LayerNorm ==========================================
template<bool OUTH>
__global__ void ln_kernel(const float* __restrict__ x,
                          const float* __restrict__ gg,
                          const float* __restrict__ bb,
                          void* __restrict__ outv)
{
    __shared__ float s1[8], s2[8], mv[2];
    long row = blockIdx.x;
    int t = threadIdx.x;
    float4 v = ((const float4*)(x + row * Dd))[t];
    float s = v.x + v.y + v.z + v.w;
    float q = v.x*v.x + v.y*v.y + v.z*v.z + v.w*v.w;
    #pragma unroll
    for (int o = 16; o > 0; o >>= 1) {
        s += __shfl_down_sync(0xffffffffu, s, o);
        q += __shfl_down_sync(0xffffffffu, q, o);
    }
    if ((t & 31) == 0) { s1[t >> 5] = s; s2[t >> 5] = q; }
    __syncthreads();
    if (t == 0) {
        float a = 0.f, c = 0.f;
        #pragma unroll
        for (int i = 0; i < 8; i++) { a += s1[i]; c += s2[i]; }
        float mu  = a * (1.0f / Dd);
        float var = c * (1.0f / Dd) - mu * mu;
        mv[0] = mu; mv[1] = rsqrtf(var + 1e-5f);
    }
    __syncthreads();
    float mu = mv[0], rs = mv[1];
    float4 gv = ((const float4*)gg)[t];
    float4 bv = ((const float4*)bb)[t];
    float o0 = (v.x - mu) * rs * gv.x + bv.x;
    float o1 = (v.y - mu) * rs * gv.y + bv.y;
    float o2 = (v.z - mu) * rs * gv.z + bv.z;
    float o3 = (v.w - mu) * rs * gv.w + bv.w;
    if (OUTH) {
        __align__(8) __half hh[4] = {__float2half(o0), __float2half(o1),
                                     __float2half(o2), __float2half(o3)};
        *(uint2*)((__half*)outv + row * Dd + t * 4) = *(uint2*)hh;
    } else {
        ((float4*)((float*)outv + row * Dd))[t] = make_float4(o0, o1, o2, o3);
    }
}

// =============== Fused QK^T + softmax (32 q-rows x 1024 keys, K=64) =========
// Each CTA: rows [m0, m0+32) of one (b,h). Warps: g = w>>2 picks 16-row group,
// wc = w&3 picks 32-col sub-block of each 128-key chunk. acc[8 chunks][4][4].
__global__ void __launch_bounds__(256)
qk_softmax(const __half* __restrict__ q, const __half* __restrict__ k,
           float* __restrict__ attn, __half* __restrict__ attn16)
{
    extern __shared__ char dsm[];
    __half (*Qs)[72] = reinterpret_cast<__half(*)[72]>(dsm);                 // 32x72
    __half (*Ks)[128][72] = reinterpret_cast<__half(*)[128][72]>(dsm + 4608); // 3 stages
    float* redm = reinterpret_cast<float*>(dsm + 4608 + 55296);              // 32x4
    float* reds = redm + 128;                                                // 32x4

    const int bh = blockIdx.y;
    const int b = bh >> 4, h = bh & 15;
    const __half* Q = q + (long)b * Ss * Dd + (long)h * 64;
    const __half* K = k + (long)b * Tt * Dd + (long)h * 64;
    const int m0 = blockIdx.x * 32;
    const int t = threadIdx.x, lane = t & 31, w = t >> 5;
    const int g = w >> 2, wc = w & 3;

    // Q tile 32x64 (group 0, together with K stage 0)
    {
        int r = t >> 3, cc = (t & 7) * 8;
        cpa16(&Qs[r][cc], Q + (long)(m0 + r) * Dd + cc);
    }
    auto loadK = [&](int buf, int ch) {
        int r = t >> 1, c0 = (t & 1) * 32;
        const __half* src = K + (long)(ch * 128 + r) * Dd + c0;
        cpa16(&Ks[buf][r][c0],      src);
        cpa16(&Ks[buf][r][c0 + 8],  src + 8);
        cpa16(&Ks[buf][r][c0 + 16], src + 16);
        cpa16(&Ks[buf][r][c0 + 24], src + 24);
    };
    loadK(0, 0); CP_COMMIT();
    loadK(1, 1); CP_COMMIT();

    float acc[8][4][4];
    #pragma unroll
    for (int i = 0; i < 8; i++)
        #pragma unroll
        for (int j = 0; j < 4; j++)
            #pragma unroll
            for (int p = 0; p < 4; p++) acc[i][j][p] = 0.f;

    const int lr16 = lane & 15, lk8 = (lane >> 4) * 8;
    for (int ch = 0; ch < 8; ch++) {
        CP_WAIT1();
        __syncthreads();
        if (ch + 2 < 8) loadK((ch + 2) % 3, ch + 2);
        CP_COMMIT();
        const int buf = ch % 3;
        #pragma unroll
        for (int ks = 0; ks < 4; ks++) {
            uint32_t a[4];
            ldmx4(a, &Qs[g * 16 + lr16][ks * 16 + lk8]);
            uint32_t bf[4][2];
            #pragma unroll
            for (int p = 0; p < 2; p++) {
                uint32_t mrr[4];
                ldmx4(mrr, &Ks[buf][wc * 32 + p * 16 + lr16][ks * 16 + lk8]);
                bf[2*p][0]   = mrr[0]; bf[2*p][1]   = mrr[2];
                bf[2*p+1][0] = mrr[1]; bf[2*p+1][1] = mrr[3];
            }
            #pragma unroll
            for (int nf = 0; nf < 4; nf++)
                mma16816(acc[ch][nf], a, bf[nf]);
        }
    }

    // ---- softmax over 1024 cols per row ----
    const int lr = lane >> 2, lc2 = (lane & 3) * 2;
    const int R0 = g * 16 + lr, R1 = R0 + 8;
    float mx0 = -1e30f, mx1 = -1e30f;
    #pragma unroll
    for (int ch = 0; ch < 8; ch++)
        #pragma unroll
        for (int nf = 0; nf < 4; nf++) {
            mx0 = fmaxf(mx0, fmaxf(acc[ch][nf][0], acc[ch][nf][1]));
            mx1 = fmaxf(mx1, fmaxf(acc[ch][nf][2], acc[ch][nf][3]));
        }
    mx0 = fmaxf(mx0, __shfl_xor_sync(0xffffffffu, mx0, 1));
    mx0 = fmaxf(mx0, __shfl_xor_sync(0xffffffffu, mx0, 2));
    mx1 = fmaxf(mx1, __shfl_xor_sync(0xffffffffu, mx1, 1));
    mx1 = fmaxf(mx1, __shfl_xor_sync(0xffffffffu, mx1, 2));
    if ((lane & 3) == 0) { redm[R0 * 4 + wc] = mx0; redm[R1 * 4 + wc] = mx1; }
    __syncthreads();
    float M0 = fmaxf(fmaxf(redm[R0*4+0], redm[R0*4+1]), fmaxf(redm[R0*4+2], redm[R0*4+3]));
    float M1 = fmaxf(fmaxf(redm[R1*4+0], redm[R1*4+1]), fmaxf(redm[R1*4+2], redm[R1*4+3]));
    float s0 = 0.f, s1 = 0.f;
    #pragma unroll
    for (int ch = 0; ch < 8; ch++)
        #pragma unroll
        for (int nf = 0; nf < 4; nf++) {
            acc[ch][nf][0] = __expf(acc[ch][nf][0] - M0);
            acc[ch][nf][1] = __expf(acc[ch][nf][1] - M0);
            acc[ch][nf][2] = __expf(acc[ch][nf][2] - M1);
            acc[ch][nf][3] = __expf(acc[ch][nf][3] - M1);
            s0 += acc[ch][nf][0] + acc[ch][nf][1];
            s1 += acc[ch][nf][2] + acc[ch][nf][3];
        }
    s0 += __shfl_xor_sync(0xffffffffu, s0, 1);
    s0 += __shfl_xor_sync(0xffffffffu, s0, 2);
    s1 += __shfl_xor_sync(0xffffffffu, s1, 1);
    s1 += __shfl_xor_sync(0xffffffffu, s1, 2);
    if ((lane & 3) == 0) { reds[R0 * 4 + wc] = s0; reds[R1 * 4 + wc] = s1; }
    __syncthreads();
    float i0 = 1.0f / (reds[R0*4+0] + reds[R0*4+1] + reds[R0*4+2] + reds[R0*4+3]);
    float i1 = 1.0f / (reds[R1*4+0] + reds[R1*4+1] + reds[R1*4+2] + reds[R1*4+3]);

    const long base = (long)bh * Ss * Tt;
    float* a0 = attn + base + (long)(m0 + R0) * Tt;
    float* a1 = attn + base + (long)(m0 + R1) * Tt;
    __half* h0 = attn16 + base + (long)(m0 + R0) * Tt;
    __half* h1 = attn16 + base + (long)(m0 + R1) * Tt;
    #pragma unroll
    for (int ch = 0; ch < 8; ch++)
        #pragma unroll
        for (int nf = 0; nf < 4; nf++) {
            int col = ch * 128 + wc * 32 + nf * 8 + lc2;
            float v0 = acc[ch][nf][0] * i0, v1 = acc[ch][nf][1] * i0;
            *(float2*)(a0 + col) = make_float2(v0, v1);
            *(__half2*)(h0 + col) = __floats2half2_rn(v0, v1);
            float u0 = acc[ch][nf][2] * i1, u1 = acc[ch][nf][3] * i1;
            *(float2*)(a1 + col) = make_float2(u0, u1);
            *(__half2*)(h1 + col) = __floats2half2_rn(u0, u1);
        }
}

// ======================= HMMA fp16 GEMM (NT, 4-stage) =======================
// C[128 x BN] per CTA. A [M,K] row-major fp16, B [N,K] row-major fp16.
// C = (A@B^T + bias)*alpha (+res)(relu); out fp16 or fp32.
template<int BN, bool CONV, bool OUTH>
__global__ void __launch_bounds__(256)
gemm_mma(const __half* __restrict__ A, int lda, long sAb, long sAh,
         const __half* __restrict__ B, int ldb, long sBb, long sBh,
         void* __restrict__ Cv, int ldc, long sCb, long sCh,
         int K, int Hdiv,
         const float* __restrict__ bias,
         const float* __restrict__ res,
         float alpha, int relu)
{
    constexpr int WGM = (BN == 128) ? 2 : 4;     // warps along M
    constexpr int WM  = 128 / WGM;               // 64 or 32
    constexpr int WN  = BN / (8 / WGM);          // 32
    constexpr int MFR = WM / 16;                 // 4 or 2
    constexpr int NFR = WN / 8;                  // 4

    extern __shared__ char dsm[];
    __half (*As)[128][40] = reinterpret_cast<__half(*)[128][40]>(dsm);
    __half (*Bs)[BN][40]  = reinterpret_cast<__half(*)[BN][40]>(dsm + 4 * 128 * 40 * 2);

    const int t = threadIdx.x;
    const int lane = t & 31;
    const int w = t >> 5;
    const int wm = (w % WGM) * WM;
    const int wn = (w / WGM) * WN;

    int z = blockIdx.z;
    int zb = z / Hdiv, zh = z - zb * Hdiv;
    A += zb * sAb + zh * sAh;
    B += zb * sBb + zh * sBh;
    const long coff = zb * sCb + zh * sCh;
    const int m0 = blockIdx.y * 128, n0 = blockIdx.x * BN;

    const int ar = t >> 1, ac = (t & 1) * 16;
    long abase = 0;
    const __half* agA = A;
    if (CONV) { int m = m0 + ar; abase = (long)((m >> 10) * SP + (m & 1023)); }
    else        agA = A + (long)(m0 + ar) * lda;

    const int br = (BN == 128) ? (t >> 1) : (t >> 2);
    const int bc = (BN == 128) ? ((t & 1) * 16) : ((t & 3) * 8);
    const __half* bg = B + (long)(n0 + br) * ldb;

    float acc[MFR][NFR][4];
    #pragma unroll
    for (int i = 0; i < MFR; i++)
        #pragma unroll
        for (int j = 0; j < NFR; j++)
            #pragma unroll
            for (int p = 0; p < 4; p++) acc[i][j][p] = 0.f;

    const int KC = K >> 5;   // BK = 32, KC >= 3 for all call sites

    auto loadbuf = [&](int buf, int k0) {
        if (CONV) {
            int kk = k0 + ac;
            int kc = kk >> 10, ci = kk & 1023;
            const __half* gp = A + (abase + kc) * (long)Dd + ci;
            cpa16(&As[buf][ar][ac],     gp);
            cpa16(&As[buf][ar][ac + 8], gp + 8);
        } else {
            const __half* gp = agA + k0 + ac;
            cpa16(&As[buf][ar][ac],     gp);
            cpa16(&As[buf][ar][ac + 8], gp + 8);
        }
        if (BN == 128) {
            const __half* gp = bg + k0 + bc;
            cpa16(&Bs[buf][br][bc],     gp);
            cpa16(&Bs[buf][br][bc + 8], gp + 8);
        } else {
            const __half* gp = bg + k0 + bc;
            cpa16(&Bs[buf][br][bc], gp);
        }
    };

    loadbuf(0, 0);  CP_COMMIT();
    loadbuf(1, 32); CP_COMMIT();
    loadbuf(2, 64); CP_COMMIT();

    const int lr16 = lane & 15;
    const int lk8  = (lane >> 4) * 8;

    for (int c = 0; c < KC; ++c) {
        CP_WAIT2();
        __syncthreads();
        if (c + 3 < KC) loadbuf((c + 3) & 3, (c + 3) * 32);
        CP_COMMIT();
        const int buf = c & 3;

        #pragma unroll
        for (int ks = 0; ks < 32; ks += 16) {
            uint32_t a[MFR][4];
            #pragma unroll
            for (int mf = 0; mf < MFR; mf++)
                ldmx4(a[mf], &As[buf][wm + mf * 16 + lr16][ks + lk8]);
            uint32_t bf[NFR][2];
            #pragma unroll
            for (int p = 0; p < NFR / 2; p++) {
                uint32_t mrr[4];
                ldmx4(mrr, &Bs[buf][wn + p * 16 + lr16][ks + lk8]);
                bf[2*p][0]   = mrr[0]; bf[2*p][1]   = mrr[2];
                bf[2*p+1][0] = mrr[1]; bf[2*p+1][1] = mrr[3];
            }
            #pragma unroll
            for (int mf = 0; mf < MFR; mf++)
                #pragma unroll
                for (int nf = 0; nf < NFR; nf++)
                    mma16816(acc[mf][nf], a[mf], bf[nf]);
        }
    }

    // ---- epilogue ----
    const int lr = lane >> 2;
    const int lc = (lane & 3) * 2;
    #pragma unroll
    for (int mf = 0; mf < MFR; mf++) {
        #pragma unroll
        for (int i = 0; i < 2; i++) {
            long mrow = m0 + wm + mf * 16 + lr + i * 8;
            #pragma unroll
            for (int nf = 0; nf < NFR; nf++) {
                int col = n0 + wn + nf * 8 + lc;
                float v0 = acc[mf][nf][i * 2 + 0];
                float v1 = acc[mf][nf][i * 2 + 1];
                if (bias) { v0 += bias[col]; v1 += bias[col + 1]; }
                v0 *= alpha; v1 *= alpha;
                if (res) {
                    float2 rv = *(const float2*)(res + coff + mrow * ldc + col);
                    v0 += rv.x; v1 += rv.y;
                }
                if (relu) { v0 = fmaxf(v0, 0.f); v1 = fmaxf(v1, 0.f); }
                if (OUTH) {
                    __half2 hv = __floats2half2_rn(v0, v1);
                    *(__half2*)((__half*)Cv + coff + mrow * ldc + col) = hv;
                } else {
                    *(float2*)((float*)Cv + coff + mrow * ldc + col) = make_float2(v0, v1);
                }
            }
        }
    }
}

// ======================= prep kernels =======================================
struct P8 { const float* p[8]; };
__global__ void cast8(P8 s, __half* __restrict__ d)
{
    long i = ((long)blockIdx.x * 256 + threadIdx.x) * 8;   // over 8*2^20
    int slab = (int)(i >> 20);
    long off = i & 0xFFFFF;
    const float* sp = s.p[slab];
    float4 a = *(const float4*)(sp + off);
    float4 b = *(const float4*)(sp + off + 4);
    __align__(16) __half h[8] = {
        __float2half(a.x), __float2half(a.y), __float2half(a.z), __float2half(a.w),
        __float2half(b.x), __float2half(b.y), __float2half(b.z), __float2half(b.w)};
    *(uint4*)(d + i) = *(uint4*)h;
}

__global__ void cast16(const float* __restrict__ s, __half* __restrict__ d, long n)
{
    long i = ((long)blockIdx.x * 256 + threadIdx.x) * 8;
    if (i >= n) return;
    float4 a = *(const float4*)(s + i);
    float4 b = *(const float4*)(s + i + 4);
    __align__(16) __half h[8] = {
        __float2half(a.x), __float2half(a.y), __float2half(a.z), __float2half(a.w),
        __float2half(b.x), __float2half(b.y), __float2half(b.z), __float2half(b.w)};
    *(uint4*)(d + i) = *(uint4*)h;
}

__global__ void pad_cast(const float* __restrict__ x, __half* __restrict__ xp)
{
    long i = (long)blockIdx.x * 256 + threadIdx.x;   // over Bb*SP*Dd
    int c = (int)(i & 1023);
    long r = i >> 10;
    int b = (int)(r / SP);
    int s = (int)(r - (long)b * SP);
    float val = 0.f;
    if (s >= 4 && s < Ss + 4) val = x[((long)b * Ss + (s - 4)) * Dd + c];
    xp[i] = __float2half(val);
}

__global__ void repack16(const float* __restrict__ w, __half* __restrict__ wp)
{
    long i = (long)blockIdx.x * 256 + threadIdx.x;   // over DHh*9216
    int kk = (int)(i % 9216);
    long n = i / 9216;
    int kc = kk >> 10, ci = kk & 1023;
    wp[i] = __float2half(w[(n * Dd + ci) * 9 + kc]);
}

// vt[b,h,n,t] = v16[b,t,h*64+n]
__global__ void transpose_v(const __half* __restrict__ v, __half* __restrict__ vt)
{
    __shared__ __half s[64][72];
    int tc = blockIdx.x, h = blockIdx.y, b = blockIdx.z;
    int t = threadIdx.x;
    int r = t >> 2;
    int c = (t & 3) * 16;
    const __half* src = v + ((long)b * Tt + tc * 64 + r) * Dd + h * 64 + c;
    *(uint4*)&s[r][c]     = *(const uint4*)src;
    *(uint4*)&s[r][c + 8] = *(const uint4*)(src + 8);
    __syncthreads();
    int n = t >> 2;
    int ts = (t & 3) * 16;
    __align__(16) __half o[16];
    #pragma unroll
    for (int j = 0; j < 16; j++) o[j] = s[ts + j][n];
    __half* dst = vt + ((long)((b * Hh + h) * 64 + n)) * Tt + tc * 64 + ts;
    *(uint4*)dst       = *(uint4*)&o[0];
    *(uint4*)(dst + 8) = *(uint4*)&o[8];
}

// ======================= launcher ===========================================
extern "C" void kernel_launch(void* const* d_in, const int* in_sizes, int n_in,
                              void* d_out, int out_size)
{
    const float* x    = (const float*)d_in[0];
    const float* xa   = (const float*)d_in[1];
    const float* Wq1  = (const float*)d_in[2];
    const float* bq1  = (const float*)d_in[3];
    const float* Wk1  = (const float*)d_in[4];
    const float* Wv1  = (const float*)d_in[5];
    const float* bv1  = (const float*)d_in[6];
    const float* Wo1  = (const float*)d_in[7];
    const float* bo1  = (const float*)d_in[8];
    const float* gln1 = (const float*)d_in[9];
    const float* bln1 = (const float*)d_in[10];
    const float* Wq2  = (const float*)d_in[11];
    const float* bq2  = (const float*)d_in[12];
    const float* Wk2  = (const float*)d_in[13];
    const float* Wv2  = (const float*)d_in[14];
    const float* bv2  = (const float*)d_in[15];
    const float* Wo2  = (const float*)d_in[16];
    const float* bo2  = (const float*)d_in[17];
    const float* gln2 = (const float*)d_in[18];
    const float* bln2 = (const float*)d_in[19];
    const float* wc1  = (const float*)d_in[20];
    const float* bc1  = (const float*)d_in[21];
    const float* wc2  = (const float*)d_in[22];
    const float* bc2  = (const float*)d_in[23];
    const float* gln3 = (const float*)d_in[24];
    const float* bln3 = (const float*)d_in[25];

    __half *h16, *q16, *k16, *v16, *vt16, *ao16, *xa16, *at16, *xp16, *y16, *wp16, *wc116, *wc216;
    float *px1, *px2, *pz, *pattn;
    cudaGetSymbolAddress((void**)&h16,   g16_h);
    cudaGetSymbolAddress((void**)&q16,   g16_q);
    cudaGetSymbolAddress((void**)&k16,   g16_k);
    cudaGetSymbolAddress((void**)&v16,   g16_v);
    cudaGetSymbolAddress((void**)&vt16,  g16_vt);
    cudaGetSymbolAddress((void**)&ao16,  g16_ao);
    cudaGetSymbolAddress((void**)&xa16,  g16_xa);
    cudaGetSymbolAddress((void**)&at16,  g16_attn);
    cudaGetSymbolAddress((void**)&xp16,  g16_xpad);
    cudaGetSymbolAddress((void**)&y16,   g16_y);
    cudaGetSymbolAddress((void**)&wp16,  g16_wp);
    cudaGetSymbolAddress((void**)&wc116, g16_wc1);
    cudaGetSymbolAddress((void**)&wc216, g16_wc2);
    cudaGetSymbolAddress((void**)&px1,   g_x1);
    cudaGetSymbolAddress((void**)&px2,   g_x2);
    cudaGetSymbolAddress((void**)&pz,    g_z);
    cudaGetSymbolAddress((void**)&pattn, g_attn);

    float* out = (float*)d_out;
    const size_t off1 = (size_t)Bb * Ss * Dd;
    const size_t asz  = (size_t)Bb * Hh * Ss * Tt;
    float* attn1 = pattn;
    float* attn2 = pattn;
    if ((size_t)out_size >= off1 + 2 * asz) {
        attn1 = out + off1;
        attn2 = out + off1 + asz;
    }

    // dynamic smem opt-in
    constexpr int SMG128 = 4 * (128 * 40 + 128 * 40) * 2;   // 81920
    constexpr int SMG64  = 4 * (128 * 40 + 64  * 40) * 2;   // 61440
    constexpr int SMQK   = 4608 + 55296 + 1024;             // 60928
    cudaFuncSetAttribute(gemm_mma<128,false,true >, cudaFuncAttributeMaxDynamicSharedMemorySize, SMG128);
    cudaFuncSetAttribute(gemm_mma<128,false,false>, cudaFuncAttributeMaxDynamicSharedMemorySize, SMG128);
    cudaFuncSetAttribute(gemm_mma<128,true ,true >, cudaFuncAttributeMaxDynamicSharedMemorySize, SMG128);
    cudaFuncSetAttribute(gemm_mma<64 ,false,true >, cudaFuncAttributeMaxDynamicSharedMemorySize, SMG64);
    cudaFuncSetAttribute(qk_softmax, cudaFuncAttributeMaxDynamicSharedMemorySize, SMQK);

    const float scale = 0.35355339059327373f;   // 64^(-0.25)
    const long MM = (long)1024 * 1024;
    dim3 blk(256);
    dim3 gproj(8, 32, 1);        // N=1024, M=4096
    dim3 gqk(32, Bb * Hh);       // 32 q-row tiles per (b,h)
    dim3 gav(1, 8, Bb * Hh);     // N=64,  M=1024 per (b,h)
    dim3 gc1(16, 32, 1);         // N=2048, M=4096
    dim3 gc2(8, 32, 1);          // N=1024, M=4096
    dim3 gtr(16, Hh, Bb);
    const long sAttnB = (long)Hh * Ss * Tt, sAttnH = (long)Ss * Tt;

    // ---- weight / input casts ----
    P8 ws; ws.p[0]=Wq1; ws.p[1]=Wk1; ws.p[2]=Wv1; ws.p[3]=Wo1;
           ws.p[4]=Wq2; ws.p[5]=Wk2; ws.p[6]=Wv2; ws.p[7]=Wo2;
    cast8<<<4096, 256>>>(ws, wp16);
    cast16<<<(int)(((long)Dd * DHh / 8 + 255) / 256), 256>>>(wc2, wc216, (long)Dd * DHh);
    cast16<<<(int)(((long)Bb * Tt * Dd / 8 + 255) / 256), 256>>>(xa, xa16, (long)Bb * Tt * Dd);
    repack16<<<(int)(((long)DHh * 9216 + 255) / 256), 256>>>(wc1, wc116);

    // ---- self attention ----
    ln_kernel<true><<<Bb * Ss, 256>>>(x, gln1, bln1, h16);
    gemm_mma<128,false,true><<<gproj, blk, SMG128>>>(h16, Dd,0,0, wp16+0*MM, Dd,0,0, q16, Dd,0,0, Dd,1, bq1, nullptr, scale, 0);
    gemm_mma<128,false,true><<<gproj, blk, SMG128>>>(h16, Dd,0,0, wp16+1*MM, Dd,0,0, k16, Dd,0,0, Dd,1, nullptr, nullptr, scale, 0);
    gemm_mma<128,false,true><<<gproj, blk, SMG128>>>(h16, Dd,0,0, wp16+2*MM, Dd,0,0, v16, Dd,0,0, Dd,1, bv1, nullptr, 1.f, 0);
    transpose_v<<<gtr, 256>>>(v16, vt16);
    qk_softmax<<<gqk, blk, SMQK>>>(q16, k16, attn1, at16);
    gemm_mma<64,false,true><<<gav, blk, SMG64>>>(at16, Tt, sAttnB, sAttnH,
        vt16, Tt, (long)Hh * 64 * Tt, (long)64 * Tt,
        ao16, Dd, (long)Ss * Dd, 64, Tt, Hh, nullptr, nullptr, 1.f, 0);
    gemm_mma<128,false,false><<<gproj, blk, SMG128>>>(ao16, Dd,0,0, wp16+3*MM, Dd,0,0, px1, Dd,0,0, Dd,1, bo1, x, 1.f, 0);

    // ---- cross attention ----
    ln_kernel<true><<<Bb * Ss, 256>>>(px1, gln2, bln2, h16);
    gemm_mma<128,false,true><<<gproj, blk, SMG128>>>(h16, Dd,0,0, wp16+4*MM, Dd,0,0, q16, Dd,0,0, Dd,1, bq2, nullptr, scale, 0);
    gemm_mma<128,false,true><<<gproj, blk, SMG128>>>(xa16, Dd,0,0, wp16+5*MM, Dd,0,0, k16, Dd,0,0, Dd,1, nullptr, nullptr, scale, 0);
    gemm_mma<128,false,true><<<gproj, blk, SMG128>>>(xa16, Dd,0,0, wp16+6*MM, Dd,0,0, v16, Dd,0,0, Dd,1, bv2, nullptr, 1.f, 0);
    transpose_v<<<gtr, 256>>>(v16, vt16);
    qk_softmax<<<gqk, blk, SMQK>>>(q16, k16, attn2, at16);
    gemm_mma<64,false,true><<<gav, blk, SMG64>>>(at16, Tt, sAttnB, sAttnH,
        vt16, Tt, (long)Hh * 64 * Tt, (long)64 * Tt,
        ao16, Dd, (long)Ss * Dd, 64, Tt, Hh, nullptr, nullptr, 1.f, 0);
    gemm_mma<128,false,false><<<gproj, blk, SMG128>>>(ao16, Dd,0,0, wp16+7*MM, Dd,0,0, px2, Dd,0,0, Dd,1, bo2, px1, 1.f, 0);

    // ---- conv FFN ----
    pad_cast<<<(Bb * SP * Dd) / 256, 256>>>(px2, xp16);
    gemm_mma<128,true,true><<<gc1, blk, SMG128>>>(xp16, Dd,0,0, wc116, 9216,0,0,
        y16, DHh,0,0, 9216, 1, bc1, nullptr, 1.f, 1);
    gemm_mma<128,false,false><<<gc2, blk, SMG128>>>(y16, DHh,0,0, wc216, DHh,0,0,
        pz, Dd,0,0, DHh, 1, bc2, px2, 1.f, 0);
    ln_kernel<false><<<Bb * Ss, 256>>>(pz, gln3, bln3, out);
}

// round 5
// speedup vs baseline: 4.9805x; 1.0448x over previous
#include <cuda_runtime.h>
#include <cuda_fp16.h>
#include <cstdint>
#include <math.h>

#define Bb 4
#define Ss 1024
#define Tt 1024
#define Dd 1024
#define Hh 16
#define DHh 2048
#define SP 1032   // S + 8 padding rows for conv1

// ======================= scratch ============================================
__device__ __half g16_h   [(size_t)Bb*Ss*Dd];
__device__ __half g16_qkv [(size_t)Bb*Ss*3072];
__device__ __half g16_vt  [(size_t)Bb*Hh*64*Tt];
__device__ __half g16_ao  [(size_t)Bb*Ss*Dd];
__device__ __half g16_xa  [(size_t)Bb*Tt*Dd];
__device__ __half g16_attn[(size_t)Bb*Hh*Ss*Tt];
__device__ __half g16_xpad[(size_t)Bb*SP*Dd];
__device__ __half g16_y   [(size_t)Bb*Ss*DHh];
__device__ __half g16_wp  [(size_t)8*Dd*Dd];
__device__ __half g16_wc1 [(size_t)DHh*9*Dd];
__device__ __half g16_wc2 [(size_t)Dd*DHh];
__device__ float  g_x1 [Bb*Ss*Dd];
__device__ float  g_x2 [Bb*Ss*Dd];
__device__ float  g_z  [Bb*Ss*Dd];
__device__ float  g_bqkv[3072];
__device__ float  g_bkv [2048];
__device__ float  g_attn[(size_t)Bb*Hh*Ss*Tt];   // fallback if attn not in d_out

// ======================= small PTX helpers ==================================
__device__ __forceinline__ void cpa16(void* s, const void* g) {
    uint32_t sa = (uint32_t)__cvta_generic_to_shared(s);
    asm volatile("cp.async.cg.shared.global [%0], [%1], 16;"
                 :: "r"(sa), "l"(__cvta_generic_to_global(g)));
}
#define CP_COMMIT() asm volatile("cp.async.commit_group;" ::: "memory")
#define CP_WAIT2()  asm volatile("cp.async.wait_group 2;" ::: "memory")
#define CP_WAIT1()  asm volatile("cp.async.wait_group 1;" ::: "memory")

__device__ __forceinline__ void ldmx4(uint32_t* r, const void* p) {
    uint32_t a = (uint32_t)__cvta_generic_to_shared(p);
    asm volatile("ldmatrix.sync.aligned.m8n8.x4.shared.b16 {%0,%1,%2,%3}, [%4];"
                 : "=r"(r[0]), "=r"(r[1]), "=r"(r[2]), "=r"(r[3]) : "r"(a));
}
__device__ __forceinline__ void mma16816(float* c, const uint32_t* a, const uint32_t* b) {
    asm volatile("mma.sync.aligned.m16n8k16.row.col.f32.f16.f16.f32 "
                 "{%0,%1,%2,%3}, {%4,%5,%6,%7}, {%8,%9}, {%0,%1,%2,%3};"
                 : "+f"(c[0]), "+f"(c[1]), "+f"(c[2]), "+f"(c[3])
                 : "r"(a[0]), "r"(a[1]), "r"(a[2]), "r"(a[3]),
                   "r"(b[0]), "r"(b[1]));
}

// ======================= LayerNorm ==========================================
template<bool OUTH>
__global__ void ln_kernel(const float* __restrict__ x,
                          const float* __restrict__ gg,
                          const float* __restrict__ bb,
                          void* __restrict__ outv)
{
    __shared__ float s1[8], s2[8], mv[2];
    long row = blockIdx.x;
    int t = threadIdx.x;
    float4 v = ((const float4*)(x + row * Dd))[t];
    float s = v.x + v.y + v.z + v.w;
    float q = v.x*v.x + v.y*v.y + v.z*v.z + v.w*v.w;
    #pragma unroll
    for (int o = 16; o > 0; o >>= 1) {
        s += __shfl_down_sync(0xffffffffu, s, o);
        q += __shfl_down_sync(0xffffffffu, q, o);
    }
    if ((t & 31) == 0) { s1[t >> 5] = s; s2[t >> 5] = q; }
    __syncthreads();
    if (t == 0) {
        float a = 0.f, c = 0.f;
        #pragma unroll
        for (int i = 0; i < 8; i++) { a += s1[i]; c += s2[i]; }
        float mu  = a * (1.0f / Dd);
        float var = c * (1.0f / Dd) - mu * mu;
        mv[0] = mu; mv[1] = rsqrtf(var + 1e-5f);
    }
    __syncthreads();
    float mu = mv[0], rs = mv[1];
    float4 gv = ((const float4*)gg)[t];
    float4 bv = ((const float4*)bb)[t];
    float o0 = (v.x - mu) * rs * gv.x + bv.x;
    float o1 = (v.y - mu) * rs * gv.y + bv.y;
    float o2 = (v.z - mu) * rs * gv.z + bv.z;
    float o3 = (v.w - mu) * rs * gv.w + bv.w;
    if (OUTH) {
        __align__(8) __half hh[4] = {__float2half(o0), __float2half(o1),
                                     __float2half(o2), __float2half(o3)};
        *(uint2*)((__half*)outv + row * Dd + t * 4) = *(uint2*)hh;
    } else {
        ((float4*)((float*)outv + row * Dd))[t] = make_float4(o0, o1, o2, o3);
    }
}

// =============== Fused QK^T + softmax (32 q-rows x 1024 keys, K=64) =========
// Q/K live inside the packed qkv buffer [B*S][3072]: q at col 0, k at col 1024.
// Logits scaled by 0.125 (= 64^-0.5) before softmax.
__global__ void __launch_bounds__(256)
qk_softmax(const __half* __restrict__ qkv,
           float* __restrict__ attn, __half* __restrict__ attn16)
{
    extern __shared__ char dsm[];
    __half (*Qs)[72] = reinterpret_cast<__half(*)[72]>(dsm);                 // 32x72
    __half (*Ks)[128][72] = reinterpret_cast<__half(*)[128][72]>(dsm + 4608); // 3 stages
    float* redm = reinterpret_cast<float*>(dsm + 4608 + 55296);              // 32x4
    float* reds = redm + 128;                                                // 32x4

    const int bh = blockIdx.y;
    const int b = bh >> 4, h = bh & 15;
    const __half* Q = qkv + (long)b * Ss * 3072 + (long)h * 64;
    const __half* K = qkv + (long)b * Ss * 3072 + 1024 + (long)h * 64;
    const int m0 = blockIdx.x * 32;
    const int t = threadIdx.x, lane = t & 31, w = t >> 5;
    const int g = w >> 2, wc = w & 3;

    {
        int r = t >> 3, cc = (t & 7) * 8;
        cpa16(&Qs[r][cc], Q + (long)(m0 + r) * 3072 + cc);
    }
    auto loadK = [&](int buf, int ch) {
        int r = t >> 1, c0 = (t & 1) * 32;
        const __half* src = K + (long)(ch * 128 + r) * 3072 + c0;
        cpa16(&Ks[buf][r][c0],      src);
        cpa16(&Ks[buf][r][c0 + 8],  src + 8);
        cpa16(&Ks[buf][r][c0 + 16], src + 16);
        cpa16(&Ks[buf][r][c0 + 24], src + 24);
    };
    loadK(0, 0); CP_COMMIT();
    loadK(1, 1); CP_COMMIT();

    float acc[8][4][4];
    #pragma unroll
    for (int i = 0; i < 8; i++)
        #pragma unroll
        for (int j = 0; j < 4; j++)
            #pragma unroll
            for (int p = 0; p < 4; p++) acc[i][j][p] = 0.f;

    const int lr16 = lane & 15, lk8 = (lane >> 4) * 8;
    for (int ch = 0; ch < 8; ch++) {
        CP_WAIT1();
        __syncthreads();
        if (ch + 2 < 8) loadK((ch + 2) % 3, ch + 2);
        CP_COMMIT();
        const int buf = ch % 3;
        #pragma unroll
        for (int ks = 0; ks < 4; ks++) {
            uint32_t a[4];
            ldmx4(a, &Qs[g * 16 + lr16][ks * 16 + lk8]);
            uint32_t bf[4][2];
            #pragma unroll
            for (int p = 0; p < 2; p++) {
                uint32_t mrr[4];
                ldmx4(mrr, &Ks[buf][wc * 32 + p * 16 + lr16][ks * 16 + lk8]);
                bf[2*p][0]   = mrr[0]; bf[2*p][1]   = mrr[2];
                bf[2*p+1][0] = mrr[1]; bf[2*p+1][1] = mrr[3];
            }
            #pragma unroll
            for (int nf = 0; nf < 4; nf++)
                mma16816(acc[ch][nf], a, bf[nf]);
        }
    }

    // scale logits by 1/8 (= dh^-0.5 for dh=64)
    #pragma unroll
    for (int ch = 0; ch < 8; ch++)
        #pragma unroll
        for (int nf = 0; nf < 4; nf++)
            #pragma unroll
            for (int p = 0; p < 4; p++) acc[ch][nf][p] *= 0.125f;

    // ---- softmax over 1024 cols per row ----
    const int lr = lane >> 2, lc2 = (lane & 3) * 2;
    const int R0 = g * 16 + lr, R1 = R0 + 8;
    float mx0 = -1e30f, mx1 = -1e30f;
    #pragma unroll
    for (int ch = 0; ch < 8; ch++)
        #pragma unroll
        for (int nf = 0; nf < 4; nf++) {
            mx0 = fmaxf(mx0, fmaxf(acc[ch][nf][0], acc[ch][nf][1]));
            mx1 = fmaxf(mx1, fmaxf(acc[ch][nf][2], acc[ch][nf][3]));
        }
    mx0 = fmaxf(mx0, __shfl_xor_sync(0xffffffffu, mx0, 1));
    mx0 = fmaxf(mx0, __shfl_xor_sync(0xffffffffu, mx0, 2));
    mx1 = fmaxf(mx1, __shfl_xor_sync(0xffffffffu, mx1, 1));
    mx1 = fmaxf(mx1, __shfl_xor_sync(0xffffffffu, mx1, 2));
    if ((lane & 3) == 0) { redm[R0 * 4 + wc] = mx0; redm[R1 * 4 + wc] = mx1; }
    __syncthreads();
    float M0 = fmaxf(fmaxf(redm[R0*4+0], redm[R0*4+1]), fmaxf(redm[R0*4+2], redm[R0*4+3]));
    float M1 = fmaxf(fmaxf(redm[R1*4+0], redm[R1*4+1]), fmaxf(redm[R1*4+2], redm[R1*4+3]));
    float s0 = 0.f, s1 = 0.f;
    #pragma unroll
    for (int ch = 0; ch < 8; ch++)
        #pragma unroll
        for (int nf = 0; nf < 4; nf++) {
            acc[ch][nf][0] = __expf(acc[ch][nf][0] - M0);
            acc[ch][nf][1] = __expf(acc[ch][nf][1] - M0);
            acc[ch][nf][2] = __expf(acc[ch][nf][2] - M1);
            acc[ch][nf][3] = __expf(acc[ch][nf][3] - M1);
            s0 += acc[ch][nf][0] + acc[ch][nf][1];
            s1 += acc[ch][nf][2] + acc[ch][nf][3];
        }
    s0 += __shfl_xor_sync(0xffffffffu, s0, 1);
    s0 += __shfl_xor_sync(0xffffffffu, s0, 2);
    s1 += __shfl_xor_sync(0xffffffffu, s1, 1);
    s1 += __shfl_xor_sync(0xffffffffu, s1, 2);
    if ((lane & 3) == 0) { reds[R0 * 4 + wc] = s0; reds[R1 * 4 + wc] = s1; }
    __syncthreads();
    float i0 = 1.0f / (reds[R0*4+0] + reds[R0*4+1] + reds[R0*4+2] + reds[R0*4+3]);
    float i1 = 1.0f / (reds[R1*4+0] + reds[R1*4+1] + reds[R1*4+2] + reds[R1*4+3]);

    const long base = (long)bh * Ss * Tt;
    float* a0 = attn + base + (long)(m0 + R0) * Tt;
    float* a1 = attn + base + (long)(m0 + R1) * Tt;
    __half* h0 = attn16 + base + (long)(m0 + R0) * Tt;
    __half* h1 = attn16 + base + (long)(m0 + R1) * Tt;
    #pragma unroll
    for (int ch = 0; ch < 8; ch++)
        #pragma unroll
        for (int nf = 0; nf < 4; nf++) {
            int col = ch * 128 + wc * 32 + nf * 8 + lc2;
            float v0 = acc[ch][nf][0] * i0, v1 = acc[ch][nf][1] * i0;
            *(float2*)(a0 + col) = make_float2(v0, v1);
            *(__half2*)(h0 + col) = __floats2half2_rn(v0, v1);
            float u0 = acc[ch][nf][2] * i1, u1 = acc[ch][nf][3] * i1;
            *(float2*)(a1 + col) = make_float2(u0, u1);
            *(__half2*)(h1 + col) = __floats2half2_rn(u0, u1);
        }
}

// ================= HMMA fp16 GEMM, 128x256 tile, 3-stage ====================
// C = A@B^T + bias (+res)(relu). A [M,K] row-major, B [N,K] row-major, fp16.
template<bool CONV, bool OUTH>
__global__ void __launch_bounds__(256, 1)
gemm256(const __half* __restrict__ A, int lda,
        const __half* __restrict__ B, int ldb,
        void* __restrict__ Cv, int ldc, int K,
        const float* __restrict__ bias,
        const float* __restrict__ res, int relu)
{
    extern __shared__ char dsm[];
    __half (*As)[128][40] = reinterpret_cast<__half(*)[128][40]>(dsm);
    __half (*Bs)[256][40] = reinterpret_cast<__half(*)[256][40]>(dsm + 3 * 128 * 40 * 2);

    const int t = threadIdx.x, lane = t & 31, w = t >> 5;
    const int wm = (w & 1) * 64;     // 2 warps along M
    const int wn = (w >> 1) * 64;    // 4 warps along N
    const int m0 = blockIdx.y * 128, n0 = blockIdx.x * 256;

    const int ar = t >> 1, ac = (t & 1) * 16;
    long abase = 0;
    const __half* agA = A;
    if (CONV) { int m = m0 + ar; abase = (long)((m >> 10) * SP + (m & 1023)); }
    else        agA = A + (long)(m0 + ar) * lda;

    const int br = t >> 1, bc = (t & 1) * 16;
    const __half* bg0 = B + (long)(n0 + br) * ldb;
    const __half* bg1 = B + (long)(n0 + br + 128) * ldb;

    float acc[4][8][4];
    #pragma unroll
    for (int i = 0; i < 4; i++)
        #pragma unroll
        for (int j = 0; j < 8; j++)
            #pragma unroll
            for (int p = 0; p < 4; p++) acc[i][j][p] = 0.f;

    const int KC = K >> 5;   // BK = 32

    auto loadbuf = [&](int buf, int k0) {
        if (CONV) {
            int kk = k0 + ac;
            int kc = kk >> 10, ci = kk & 1023;
            const __half* gp = A + (abase + kc) * (long)Dd + ci;
            cpa16(&As[buf][ar][ac],     gp);
            cpa16(&As[buf][ar][ac + 8], gp + 8);
        } else {
            const __half* gp = agA + k0 + ac;
            cpa16(&As[buf][ar][ac],     gp);
            cpa16(&As[buf][ar][ac + 8], gp + 8);
        }
        cpa16(&Bs[buf][br][bc],           bg0 + k0 + bc);
        cpa16(&Bs[buf][br][bc + 8],       bg0 + k0 + bc + 8);
        cpa16(&Bs[buf][br + 128][bc],     bg1 + k0 + bc);
        cpa16(&Bs[buf][br + 128][bc + 8], bg1 + k0 + bc + 8);
    };

    loadbuf(0, 0);  CP_COMMIT();
    loadbuf(1, 32); CP_COMMIT();

    const int lr16 = lane & 15;
    const int lk8  = (lane >> 4) * 8;

    for (int c = 0; c < KC; ++c) {
        CP_WAIT1();
        __syncthreads();
        if (c + 2 < KC) loadbuf((c + 2) % 3, (c + 2) * 32);
        CP_COMMIT();
        const int buf = c % 3;

        #pragma unroll
        for (int ks = 0; ks < 32; ks += 16) {
            uint32_t a[4][4];
            #pragma unroll
            for (int mf = 0; mf < 4; mf++)
                ldmx4(a[mf], &As[buf][wm + mf * 16 + lr16][ks + lk8]);
            uint32_t bf[8][2];
            #pragma unroll
            for (int p = 0; p < 4; p++) {
                uint32_t mrr[4];
                ldmx4(mrr, &Bs[buf][wn + p * 16 + lr16][ks + lk8]);
                bf[2*p][0]   = mrr[0]; bf[2*p][1]   = mrr[2];
                bf[2*p+1][0] = mrr[1]; bf[2*p+1][1] = mrr[3];
            }
            #pragma unroll
            for (int mf = 0; mf < 4; mf++)
                #pragma unroll
                for (int nf = 0; nf < 8; nf++)
                    mma16816(acc[mf][nf], a[mf], bf[nf]);
        }
    }

    // ---- epilogue ----
    const int lr = lane >> 2;
    const int lc = (lane & 3) * 2;
    #pragma unroll
    for (int mf = 0; mf < 4; mf++) {
        #pragma unroll
        for (int i = 0; i < 2; i++) {
            long mrow = m0 + wm + mf * 16 + lr + i * 8;
            #pragma unroll
            for (int nf = 0; nf < 8; nf++) {
                int col = n0 + wn + nf * 8 + lc;
                float v0 = acc[mf][nf][i * 2 + 0];
                float v1 = acc[mf][nf][i * 2 + 1];
                if (bias) { v0 += bias[col]; v1 += bias[col + 1]; }
                if (res) {
                    float2 rv = *(const float2*)(res + mrow * ldc + col);
                    v0 += rv.x; v1 += rv.y;
                }
                if (relu) { v0 = fmaxf(v0, 0.f); v1 = fmaxf(v1, 0.f); }
                if (OUTH) {
                    *(__half2*)((__half*)Cv + mrow * ldc + col) = __floats2half2_rn(v0, v1);
                } else {
                    *(float2*)((float*)Cv + mrow * ldc + col) = make_float2(v0, v1);
                }
            }
        }
    }
}

// ================= HMMA fp16 GEMM (NT, 4-stage) — used for AV ===============
template<int BN, bool OUTH>
__global__ void __launch_bounds__(256)
gemm_mma(const __half* __restrict__ A, int lda, long sAb, long sAh,
         const __half* __restrict__ B, int ldb, long sBb, long sBh,
         void* __restrict__ Cv, int ldc, long sCb, long sCh,
         int K, int Hdiv)
{
    constexpr int WGM = 4;
    constexpr int WM  = 32;
    constexpr int WN  = BN / 2;
    constexpr int MFR = WM / 16;
    constexpr int NFR = WN / 8;

    extern __shared__ char dsm[];
    __half (*As)[128][40] = reinterpret_cast<__half(*)[128][40]>(dsm);
    __half (*Bs)[BN][40]  = reinterpret_cast<__half(*)[BN][40]>(dsm + 4 * 128 * 40 * 2);

    const int t = threadIdx.x;
    const int lane = t & 31;
    const int w = t >> 5;
    const int wm = (w % WGM) * WM;
    const int wn = (w / WGM) * WN;

    int z = blockIdx.z;
    int zb = z / Hdiv, zh = z - zb * Hdiv;
    A += zb * sAb + zh * sAh;
    B += zb * sBb + zh * sBh;
    const long coff = zb * sCb + zh * sCh;
    const int m0 = blockIdx.y * 128, n0 = blockIdx.x * BN;

    const int ar = t >> 1, ac = (t & 1) * 16;
    const __half* agA = A + (long)(m0 + ar) * lda;
    const int br = t >> 2;
    const int bc = (t & 3) * 8;
    const __half* bg = B + (long)(n0 + br) * ldb;

    float acc[MFR][NFR][4];
    #pragma unroll
    for (int i = 0; i < MFR; i++)
        #pragma unroll
        for (int j = 0; j < NFR; j++)
            #pragma unroll
            for (int p = 0; p < 4; p++) acc[i][j][p] = 0.f;

    const int KC = K >> 5;

    auto loadbuf = [&](int buf, int k0) {
        const __half* gp = agA + k0 + ac;
        cpa16(&As[buf][ar][ac],     gp);
        cpa16(&As[buf][ar][ac + 8], gp + 8);
        cpa16(&Bs[buf][br][bc], bg + k0 + bc);
    };

    loadbuf(0, 0);  CP_COMMIT();
    loadbuf(1, 32); CP_COMMIT();
    loadbuf(2, 64); CP_COMMIT();

    const int lr16 = lane & 15;
    const int lk8  = (lane >> 4) * 8;

    for (int c = 0; c < KC; ++c) {
        CP_WAIT2();
        __syncthreads();
        if (c + 3 < KC) loadbuf((c + 3) & 3, (c + 3) * 32);
        CP_COMMIT();
        const int buf = c & 3;

        #pragma unroll
        for (int ks = 0; ks < 32; ks += 16) {
            uint32_t a[MFR][4];
            #pragma unroll
            for (int mf = 0; mf < MFR; mf++)
                ldmx4(a[mf], &As[buf][wm + mf * 16 + lr16][ks + lk8]);
            uint32_t bf[NFR][2];
            #pragma unroll
            for (int p = 0; p < NFR / 2; p++) {
                uint32_t mrr[4];
                ldmx4(mrr, &Bs[buf][wn + p * 16 + lr16][ks + lk8]);
                bf[2*p][0]   = mrr[0]; bf[2*p][1]   = mrr[2];
                bf[2*p+1][0] = mrr[1]; bf[2*p+1][1] = mrr[3];
            }
            #pragma unroll
            for (int mf = 0; mf < MFR; mf++)
                #pragma unroll
                for (int nf = 0; nf < NFR; nf++)
                    mma16816(acc[mf][nf], a[mf], bf[nf]);
        }
    }

    const int lr = lane >> 2;
    const int lc = (lane & 3) * 2;
    #pragma unroll
    for (int mf = 0; mf < MFR; mf++) {
        #pragma unroll
        for (int i = 0; i < 2; i++) {
            long mrow = m0 + wm + mf * 16 + lr + i * 8;
            #pragma unroll
            for (int nf = 0; nf < NFR; nf++) {
                int col = n0 + wn + nf * 8 + lc;
                float v0 = acc[mf][nf][i * 2 + 0];
                float v1 = acc[mf][nf][i * 2 + 1];
                if (OUTH) {
                    *(__half2*)((__half*)Cv + coff + mrow * ldc + col) = __floats2half2_rn(v0, v1);
                } else {
                    *(float2*)((float*)Cv + coff + mrow * ldc + col) = make_float2(v0, v1);
                }
            }
        }
    }
}

// ======================= prep kernels =======================================
struct P8 { const float* p[8]; };
__global__ void cast8(P8 s, __half* __restrict__ d)
{
    long i = ((long)blockIdx.x * 256 + threadIdx.x) * 8;   // over 8*2^20
    int slab = (int)(i >> 20);
    long off = i & 0xFFFFF;
    const float* sp = s.p[slab];
    float4 a = *(const float4*)(sp + off);
    float4 b = *(const float4*)(sp + off + 4);
    __align__(16) __half h[8] = {
        __float2half(a.x), __float2half(a.y), __float2half(a.z), __float2half(a.w),
        __float2half(b.x), __float2half(b.y), __float2half(b.z), __float2half(b.w)};
    *(uint4*)(d + i) = *(uint4*)h;
}

__global__ void cast16(const float* __restrict__ s, __half* __restrict__ d, long n)
{
    long i = ((long)blockIdx.x * 256 + threadIdx.x) * 8;
    if (i >= n) return;
    float4 a = *(const float4*)(s + i);
    float4 b = *(const float4*)(s + i + 4);
    __align__(16) __half h[8] = {
        __float2half(a.x), __float2half(a.y), __float2half(a.z), __float2half(a.w),
        __float2half(b.x), __float2half(b.y), __float2half(b.z), __float2half(b.w)};
    *(uint4*)(d + i) = *(uint4*)h;
}

__global__ void pad_cast(const float* __restrict__ x, __half* __restrict__ xp)
{
    long i = (long)blockIdx.x * 256 + threadIdx.x;   // over Bb*SP*Dd
    int c = (int)(i & 1023);
    long r = i >> 10;
    int b = (int)(r / SP);
    int s = (int)(r - (long)b * SP);
    float val = 0.f;
    if (s >= 4 && s < Ss + 4) val = x[((long)b * Ss + (s - 4)) * Dd + c];
    xp[i] = __float2half(val);
}

// conv1 weight repack via smem transpose: wp[n][kc][ci] = w[n][ci][kc]
__global__ void repack_t(const float* __restrict__ w, __half* __restrict__ wp)
{
    __shared__ float s[9216];
    long n = blockIdx.x;            // 0..DHh-1
    const float* src = w + n * 9216;
    for (int j = threadIdx.x; j < 9216; j += 256) s[j] = src[j];
    __syncthreads();
    __half* dst = wp + n * 9216;
    for (int j = threadIdx.x; j < 9216; j += 256) {
        int kc = j >> 10, ci = j & 1023;
        dst[j] = __float2half(s[ci * 9 + kc]);
    }
}

// merged bias vectors: bqkv = [bq1 | 0 | bv1], bkv = [0 | bv2]
__global__ void build_bias(const float* __restrict__ bq1, const float* __restrict__ bv1,
                           const float* __restrict__ bv2,
                           float* __restrict__ bqkv, float* __restrict__ bkv)
{
    int i = blockIdx.x * 256 + threadIdx.x;   // 0..5119
    if (i < 3072) {
        float v = 0.f;
        if (i < 1024) v = bq1[i];
        else if (i >= 2048) v = bv1[i - 2048];
        bqkv[i] = v;
    } else if (i < 5120) {
        int j = i - 3072;
        bkv[j] = (j < 1024) ? 0.f : bv2[j - 1024];
    }
}

// vt[b,h,n,t] = qkv[b,t, 2048 + h*64 + n]
__global__ void transpose_v(const __half* __restrict__ qkv, __half* __restrict__ vt)
{
    __shared__ __half s[64][72];
    int tc = blockIdx.x, h = blockIdx.y, b = blockIdx.z;
    int t = threadIdx.x;
    int r = t >> 2;
    int c = (t & 3) * 16;
    const __half* src = qkv + ((long)b * Tt + tc * 64 + r) * 3072 + 2048 + h * 64 + c;
    *(uint4*)&s[r][c]     = *(const uint4*)src;
    *(uint4*)&s[r][c + 8] = *(const uint4*)(src + 8);
    __syncthreads();
    int n = t >> 2;
    int ts = (t & 3) * 16;
    __align__(16) __half o[16];
    #pragma unroll
    for (int j = 0; j < 16; j++) o[j] = s[ts + j][n];
    __half* dst = vt + ((long)((b * Hh + h) * 64 + n)) * Tt + tc * 64 + ts;
    *(uint4*)dst       = *(uint4*)&o[0];
    *(uint4*)(dst + 8) = *(uint4*)&o[8];
}

// ======================= launcher ===========================================
extern "C" void kernel_launch(void* const* d_in, const int* in_sizes, int n_in,
                              void* d_out, int out_size)
{
    const float* x    = (const float*)d_in[0];
    const float* xa   = (const float*)d_in[1];
    const float* Wq1  = (const float*)d_in[2];
    const float* bq1  = (const float*)d_in[3];
    const float* Wk1  = (const float*)d_in[4];
    const float* Wv1  = (const float*)d_in[5];
    const float* bv1  = (const float*)d_in[6];
    const float* Wo1  = (const float*)d_in[7];
    const float* bo1  = (const float*)d_in[8];
    const float* gln1 = (const float*)d_in[9];
    const float* bln1 = (const float*)d_in[10];
    const float* Wq2  = (const float*)d_in[11];
    const float* bq2  = (const float*)d_in[12];
    const float* Wk2  = (const float*)d_in[13];
    const float* Wv2  = (const float*)d_in[14];
    const float* bv2  = (const float*)d_in[15];
    const float* Wo2  = (const float*)d_in[16];
    const float* bo2  = (const float*)d_in[17];
    const float* gln2 = (const float*)d_in[18];
    const float* bln2 = (const float*)d_in[19];
    const float* wc1  = (const float*)d_in[20];
    const float* bc1  = (const float*)d_in[21];
    const float* wc2  = (const float*)d_in[22];
    const float* bc2  = (const float*)d_in[23];
    const float* gln3 = (const float*)d_in[24];
    const float* bln3 = (const float*)d_in[25];

    __half *h16, *qkv16, *vt16, *ao16, *xa16, *at16, *xp16, *y16, *wp16, *wc116, *wc216;
    float *px1, *px2, *pz, *pattn, *pbqkv, *pbkv;
    cudaGetSymbolAddress((void**)&h16,   g16_h);
    cudaGetSymbolAddress((void**)&qkv16, g16_qkv);
    cudaGetSymbolAddress((void**)&vt16,  g16_vt);
    cudaGetSymbolAddress((void**)&ao16,  g16_ao);
    cudaGetSymbolAddress((void**)&xa16,  g16_xa);
    cudaGetSymbolAddress((void**)&at16,  g16_attn);
    cudaGetSymbolAddress((void**)&xp16,  g16_xpad);
    cudaGetSymbolAddress((void**)&y16,   g16_y);
    cudaGetSymbolAddress((void**)&wp16,  g16_wp);
    cudaGetSymbolAddress((void**)&wc116, g16_wc1);
    cudaGetSymbolAddress((void**)&wc216, g16_wc2);
    cudaGetSymbolAddress((void**)&px1,   g_x1);
    cudaGetSymbolAddress((void**)&px2,   g_x2);
    cudaGetSymbolAddress((void**)&pz,    g_z);
    cudaGetSymbolAddress((void**)&pattn, g_attn);
    cudaGetSymbolAddress((void**)&pbqkv, g_bqkv);
    cudaGetSymbolAddress((void**)&pbkv,  g_bkv);

    float* out = (float*)d_out;
    const size_t off1 = (size_t)Bb * Ss * Dd;
    const size_t asz  = (size_t)Bb * Hh * Ss * Tt;
    float* attn1 = pattn;
    float* attn2 = pattn;
    if ((size_t)out_size >= off1 + 2 * asz) {
        attn1 = out + off1;
        attn2 = out + off1 + asz;
    }

    // dynamic smem opt-in
    constexpr int SM256 = 3 * (128 * 40 + 256 * 40) * 2;    // 92160
    constexpr int SMG64 = 4 * (128 * 40 + 64  * 40) * 2;    // 61440
    constexpr int SMQK  = 4608 + 55296 + 1024;              // 60928
    cudaFuncSetAttribute(gemm256<false,true >, cudaFuncAttributeMaxDynamicSharedMemorySize, SM256);
    cudaFuncSetAttribute(gemm256<false,false>, cudaFuncAttributeMaxDynamicSharedMemorySize, SM256);
    cudaFuncSetAttribute(gemm256<true ,true >, cudaFuncAttributeMaxDynamicSharedMemorySize, SM256);
    cudaFuncSetAttribute(gemm_mma<64,true>, cudaFuncAttributeMaxDynamicSharedMemorySize, SMG64);
    cudaFuncSetAttribute(qk_softmax, cudaFuncAttributeMaxDynamicSharedMemorySize, SMQK);

    const long MM = (long)1024 * 1024;
    dim3 blk(256);
    dim3 gqkv(12, 32);           // N=3072, M=4096
    dim3 gq(4, 32);              // N=1024
    dim3 gkv(8, 32);             // N=2048
    dim3 go(4, 32);              // N=1024
    dim3 gqk(32, Bb * Hh);
    dim3 gav(1, 8, Bb * Hh);
    dim3 gc1(8, 32);             // N=2048
    dim3 gc2(4, 32);             // N=1024
    dim3 gtr(16, Hh, Bb);
    const long sAttnB = (long)Hh * Ss * Tt, sAttnH = (long)Ss * Tt;

    // ---- prep: weights, biases ----
    P8 ws; ws.p[0]=Wq1; ws.p[1]=Wk1; ws.p[2]=Wv1; ws.p[3]=Wo1;
           ws.p[4]=Wq2; ws.p[5]=Wk2; ws.p[6]=Wv2; ws.p[7]=Wo2;
    cast8<<<4096, 256>>>(ws, wp16);
    cast16<<<(int)(((long)Dd * DHh / 8 + 255) / 256), 256>>>(wc2, wc216, (long)Dd * DHh);
    cast16<<<(int)(((long)Bb * Tt * Dd / 8 + 255) / 256), 256>>>(xa, xa16, (long)Bb * Tt * Dd);
    repack_t<<<DHh, 256>>>(wc1, wc116);
    build_bias<<<20, 256>>>(bq1, bv1, bv2, pbqkv, pbkv);

    // ---- self attention ----
    ln_kernel<true><<<Bb * Ss, 256>>>(x, gln1, bln1, h16);
    gemm256<false,true><<<gqkv, blk, SM256>>>(h16, Dd, wp16, Dd,
        qkv16, 3072, Dd, pbqkv, nullptr, 0);
    transpose_v<<<gtr, 256>>>(qkv16, vt16);
    qk_softmax<<<gqk, blk, SMQK>>>(qkv16, attn1, at16);
    gemm_mma<64,true><<<gav, blk, SMG64>>>(at16, Tt, sAttnB, sAttnH,
        vt16, Tt, (long)Hh * 64 * Tt, (long)64 * Tt,
        ao16, Dd, (long)Ss * Dd, 64, Tt, Hh);
    gemm256<false,false><<<go, blk, SM256>>>(ao16, Dd, wp16 + 3 * MM, Dd,
        px1, Dd, Dd, bo1, x, 0);

    // ---- cross attention ----
    ln_kernel<true><<<Bb * Ss, 256>>>(px1, gln2, bln2, h16);
    gemm256<false,true><<<gq, blk, SM256>>>(h16, Dd, wp16 + 4 * MM, Dd,
        qkv16, 3072, Dd, bq2, nullptr, 0);
    gemm256<false,true><<<gkv, blk, SM256>>>(xa16, Dd, wp16 + 5 * MM, Dd,
        qkv16 + 1024, 3072, Dd, pbkv, nullptr, 0);
    transpose_v<<<gtr, 256>>>(qkv16, vt16);
    qk_softmax<<<gqk, blk, SMQK>>>(qkv16, attn2, at16);
    gemm_mma<64,true><<<gav, blk, SMG64>>>(at16, Tt, sAttnB, sAttnH,
        vt16, Tt, (long)Hh * 64 * Tt, (long)64 * Tt,
        ao16, Dd, (long)Ss * Dd, 64, Tt, Hh);
    gemm256<false,false><<<go, blk, SM256>>>(ao16, Dd, wp16 + 7 * MM, Dd,
        px2, Dd, Dd, bo2, px1, 0);

    // ---- conv FFN ----
    pad_cast<<<(Bb * SP * Dd) / 256, 256>>>(px2, xp16);
    gemm256<true,true><<<gc1, blk, SM256>>>(xp16, Dd, wc116, 9216,
        y16, DHh, 9216, bc1, nullptr, 1);
    gemm256<false,false><<<gc2, blk, SM256>>>(y16, DHh, wc216, DHh,
        pz, Dd, DHh, bc2, px2, 0);
    ln_kernel<false><<<Bb * Ss, 256>>>(pz, gln3, bln3, out);
}

// round 6
// speedup vs baseline: 5.0738x; 1.0187x over previous
#include <cuda_runtime.h>
#include <cuda_fp16.h>
#include <cstdint>
#include <math.h>

#define Bb 4
#define Ss 1024
#define Tt 1024
#define Dd 1024
#define Hh 16
#define DHh 2048
#define SP 1032   // S + 8 padding rows for conv1

// ======================= scratch ============================================
__device__ __half g16_h   [(size_t)Bb*Ss*Dd];
__device__ __half g16_qkv [(size_t)Bb*Ss*3072];
__device__ __half g16_ao  [(size_t)Bb*Ss*Dd];
__device__ __half g16_xa  [(size_t)Bb*Tt*Dd];
__device__ __half g16_xpad[(size_t)Bb*SP*Dd];
__device__ __half g16_y   [(size_t)Bb*Ss*DHh];
__device__ __half g16_wp  [(size_t)8*Dd*Dd];
__device__ __half g16_wc1 [(size_t)DHh*9*Dd];
__device__ __half g16_wc2 [(size_t)Dd*DHh];
__device__ float  g_x1 [Bb*Ss*Dd];
__device__ float  g_x2 [Bb*Ss*Dd];
__device__ float  g_z  [Bb*Ss*Dd];
__device__ float  g_bqkv[3072];
__device__ float  g_bkv [2048];
__device__ float  g_attn[(size_t)Bb*Hh*Ss*Tt];   // fallback if attn not in d_out

// ======================= small PTX helpers ==================================
__device__ __forceinline__ void cpa16(void* s, const void* g) {
    uint32_t sa = (uint32_t)__cvta_generic_to_shared(s);
    asm volatile("cp.async.cg.shared.global [%0], [%1], 16;"
                 :: "r"(sa), "l"(__cvta_generic_to_global(g)));
}
#define CP_COMMIT() asm volatile("cp.async.commit_group;" ::: "memory")
#define CP_WAIT2()  asm volatile("cp.async.wait_group 2;" ::: "memory")
#define CP_WAIT1()  asm volatile("cp.async.wait_group 1;" ::: "memory")

__device__ __forceinline__ void ldmx4(uint32_t* r, const void* p) {
    uint32_t a = (uint32_t)__cvta_generic_to_shared(p);
    asm volatile("ldmatrix.sync.aligned.m8n8.x4.shared.b16 {%0,%1,%2,%3}, [%4];"
                 : "=r"(r[0]), "=r"(r[1]), "=r"(r[2]), "=r"(r[3]) : "r"(a));
}
__device__ __forceinline__ void ldmx4t(uint32_t* r, const void* p) {
    uint32_t a = (uint32_t)__cvta_generic_to_shared(p);
    asm volatile("ldmatrix.sync.aligned.m8n8.x4.trans.shared.b16 {%0,%1,%2,%3}, [%4];"
                 : "=r"(r[0]), "=r"(r[1]), "=r"(r[2]), "=r"(r[3]) : "r"(a));
}
__device__ __forceinline__ void mma16816(float* c, const uint32_t* a, const uint32_t* b) {
    asm volatile("mma.sync.aligned.m16n8k16.row.col.f32.f16.f16.f32 "
                 "{%0,%1,%2,%3}, {%4,%5,%6,%7}, {%8,%9}, {%0,%1,%2,%3};"
                 : "+f"(c[0]), "+f"(c[1]), "+f"(c[2]), "+f"(c[3])
                 : "r"(a[0]), "r"(a[1]), "r"(a[2]), "r"(a[3]),
                   "r"(b[0]), "r"(b[1]));
}
__device__ __forceinline__ uint32_t packh2(float a, float b) {
    __half2 h = __floats2half2_rn(a, b);
    return *(uint32_t*)&h;
}

// ======================= LayerNorm ==========================================
template<bool OUTH>
__global__ void ln_kernel(const float* __restrict__ x,
                          const float* __restrict__ gg,
                          const float* __restrict__ bb,
                          void* __restrict__ outv)
{
    __shared__ float s1[8], s2[8], mv[2];
    long row = blockIdx.x;
    int t = threadIdx.x;
    float4 v = ((const float4*)(x + row * Dd))[t];
    float s = v.x + v.y + v.z + v.w;
    float q = v.x*v.x + v.y*v.y + v.z*v.z + v.w*v.w;
    #pragma unroll
    for (int o = 16; o > 0; o >>= 1) {
        s += __shfl_down_sync(0xffffffffu, s, o);
        q += __shfl_down_sync(0xffffffffu, q, o);
    }
    if ((t & 31) == 0) { s1[t >> 5] = s; s2[t >> 5] = q; }
    __syncthreads();
    if (t == 0) {
        float a = 0.f, c = 0.f;
        #pragma unroll
        for (int i = 0; i < 8; i++) { a += s1[i]; c += s2[i]; }
        float mu  = a * (1.0f / Dd);
        float var = c * (1.0f / Dd) - mu * mu;
        mv[0] = mu; mv[1] = rsqrtf(var + 1e-5f);
    }
    __syncthreads();
    float mu = mv[0], rs = mv[1];
    float4 gv = ((const float4*)gg)[t];
    float4 bv = ((const float4*)bb)[t];
    float o0 = (v.x - mu) * rs * gv.x + bv.x;
    float o1 = (v.y - mu) * rs * gv.y + bv.y;
    float o2 = (v.z - mu) * rs * gv.z + bv.z;
    float o3 = (v.w - mu) * rs * gv.w + bv.w;
    if (OUTH) {
        __align__(8) __half hh[4] = {__float2half(o0), __float2half(o1),
                                     __float2half(o2), __float2half(o3)};
        *(uint2*)((__half*)outv + row * Dd + t * 4) = *(uint2*)hh;
    } else {
        ((float4*)((float*)outv + row * Dd))[t] = make_float4(o0, o1, o2, o3);
    }
}

// ========== Fused QK^T + softmax + P@V (flash-style, 32 q-rows/CTA) =========
// qkv packed [B*S][3072]: q col 0, k col 1024, v col 2048. Logits *0.125.
// Outputs: attn fp32 [bh][S][T] and O fp16 into ao[b][s][h*64+dh].
__global__ void __launch_bounds__(256)
qk_sm_av(const __half* __restrict__ qkv,
         float* __restrict__ attn, __half* __restrict__ ao)
{
    extern __shared__ char dsm[];
    __half (*Qs)[72] = reinterpret_cast<__half(*)[72]>(dsm);                  // 32x72
    __half (*KV)[128][72] = reinterpret_cast<__half(*)[128][72]>(dsm + 4608); // 3 stages
    float* redm = reinterpret_cast<float*>(dsm + 60416 - 512);                // 32x4
    float* reds = redm + 128;                                                 // 32x4
    float* Po   = reinterpret_cast<float*>(dsm + 60416);                      // 4x32x64

    const int bh = blockIdx.y;
    const int b = bh >> 4, h = bh & 15;
    const __half* Q = qkv + (long)b * Ss * 3072 + (long)h * 64;
    const __half* K = Q + 1024;
    const __half* V = Q + 2048;
    const int m0 = blockIdx.x * 32;
    const int t = threadIdx.x, lane = t & 31, w = t >> 5;
    const int g = w >> 2, wc = w & 3;

    {
        int r = t >> 3, cc = (t & 7) * 8;
        cpa16(&Qs[r][cc], Q + (long)(m0 + r) * 3072 + cc);
    }
    const int ldr = t >> 1, ldc0 = (t & 1) * 32;
    auto loadT = [&](const __half* src0, int buf, int ch) {
        const __half* src = src0 + (long)(ch * 128 + ldr) * 3072 + ldc0;
        cpa16(&KV[buf][ldr][ldc0],      src);
        cpa16(&KV[buf][ldr][ldc0 + 8],  src + 8);
        cpa16(&KV[buf][ldr][ldc0 + 16], src + 16);
        cpa16(&KV[buf][ldr][ldc0 + 24], src + 24);
    };
    loadT(K, 0, 0); CP_COMMIT();
    loadT(K, 1, 1); CP_COMMIT();

    float acc[8][4][4];
    #pragma unroll
    for (int i = 0; i < 8; i++)
        #pragma unroll
        for (int j = 0; j < 4; j++)
            #pragma unroll
            for (int p = 0; p < 4; p++) acc[i][j][p] = 0.f;

    const int lr16 = lane & 15, lk8 = (lane >> 4) * 8;
    for (int ch = 0; ch < 8; ch++) {
        CP_WAIT1();
        __syncthreads();
        if (ch + 2 < 8) loadT(K, (ch + 2) % 3, ch + 2);
        CP_COMMIT();
        const int buf = ch % 3;
        #pragma unroll
        for (int ks = 0; ks < 4; ks++) {
            uint32_t a[4];
            ldmx4(a, &Qs[g * 16 + lr16][ks * 16 + lk8]);
            uint32_t bf[4][2];
            #pragma unroll
            for (int p = 0; p < 2; p++) {
                uint32_t mrr[4];
                ldmx4(mrr, &KV[buf][wc * 32 + p * 16 + lr16][ks * 16 + lk8]);
                bf[2*p][0]   = mrr[0]; bf[2*p][1]   = mrr[2];
                bf[2*p+1][0] = mrr[1]; bf[2*p+1][1] = mrr[3];
            }
            #pragma unroll
            for (int nf = 0; nf < 4; nf++)
                mma16816(acc[ch][nf], a, bf[nf]);
        }
    }

    // ---- softmax over 1024 cols per row (logit scale 1/8) ----
    const int lr = lane >> 2, lc2 = (lane & 3) * 2;
    const int R0 = g * 16 + lr, R1 = R0 + 8;
    float mx0 = -1e30f, mx1 = -1e30f;
    #pragma unroll
    for (int ch = 0; ch < 8; ch++)
        #pragma unroll
        for (int nf = 0; nf < 4; nf++) {
            #pragma unroll
            for (int p = 0; p < 4; p++) acc[ch][nf][p] *= 0.125f;
            mx0 = fmaxf(mx0, fmaxf(acc[ch][nf][0], acc[ch][nf][1]));
            mx1 = fmaxf(mx1, fmaxf(acc[ch][nf][2], acc[ch][nf][3]));
        }
    mx0 = fmaxf(mx0, __shfl_xor_sync(0xffffffffu, mx0, 1));
    mx0 = fmaxf(mx0, __shfl_xor_sync(0xffffffffu, mx0, 2));
    mx1 = fmaxf(mx1, __shfl_xor_sync(0xffffffffu, mx1, 1));
    mx1 = fmaxf(mx1, __shfl_xor_sync(0xffffffffu, mx1, 2));
    if ((lane & 3) == 0) { redm[R0 * 4 + wc] = mx0; redm[R1 * 4 + wc] = mx1; }
    __syncthreads();                       // all warps done with KV smem too
    // start streaming V while we finish the softmax
    loadT(V, 0, 0); CP_COMMIT();
    loadT(V, 1, 1); CP_COMMIT();

    float M0 = fmaxf(fmaxf(redm[R0*4+0], redm[R0*4+1]), fmaxf(redm[R0*4+2], redm[R0*4+3]));
    float M1 = fmaxf(fmaxf(redm[R1*4+0], redm[R1*4+1]), fmaxf(redm[R1*4+2], redm[R1*4+3]));
    float s0 = 0.f, s1 = 0.f;
    #pragma unroll
    for (int ch = 0; ch < 8; ch++)
        #pragma unroll
        for (int nf = 0; nf < 4; nf++) {
            acc[ch][nf][0] = __expf(acc[ch][nf][0] - M0);
            acc[ch][nf][1] = __expf(acc[ch][nf][1] - M0);
            acc[ch][nf][2] = __expf(acc[ch][nf][2] - M1);
            acc[ch][nf][3] = __expf(acc[ch][nf][3] - M1);
            s0 += acc[ch][nf][0] + acc[ch][nf][1];
            s1 += acc[ch][nf][2] + acc[ch][nf][3];
        }
    s0 += __shfl_xor_sync(0xffffffffu, s0, 1);
    s0 += __shfl_xor_sync(0xffffffffu, s0, 2);
    s1 += __shfl_xor_sync(0xffffffffu, s1, 1);
    s1 += __shfl_xor_sync(0xffffffffu, s1, 2);
    if ((lane & 3) == 0) { reds[R0 * 4 + wc] = s0; reds[R1 * 4 + wc] = s1; }
    __syncthreads();
    float i0 = 1.0f / (reds[R0*4+0] + reds[R0*4+1] + reds[R0*4+2] + reds[R0*4+3]);
    float i1 = 1.0f / (reds[R1*4+0] + reds[R1*4+1] + reds[R1*4+2] + reds[R1*4+3]);

    // normalize in place + write fp32 attention output
    const long base = (long)bh * Ss * Tt;
    float* a0 = attn + base + (long)(m0 + R0) * Tt;
    float* a1 = attn + base + (long)(m0 + R1) * Tt;
    #pragma unroll
    for (int ch = 0; ch < 8; ch++)
        #pragma unroll
        for (int nf = 0; nf < 4; nf++) {
            int col = ch * 128 + wc * 32 + nf * 8 + lc2;
            acc[ch][nf][0] *= i0; acc[ch][nf][1] *= i0;
            acc[ch][nf][2] *= i1; acc[ch][nf][3] *= i1;
            *(float2*)(a0 + col) = make_float2(acc[ch][nf][0], acc[ch][nf][1]);
            *(float2*)(a1 + col) = make_float2(acc[ch][nf][2], acc[ch][nf][3]);
        }

    // ---- P @ V: each warp covers its 256 keys; partial O in registers -----
    float oacc[8][4];
    #pragma unroll
    for (int nb = 0; nb < 8; nb++)
        #pragma unroll
        for (int p = 0; p < 4; p++) oacc[nb][p] = 0.f;

    for (int ch = 0; ch < 8; ch++) {
        CP_WAIT1();
        __syncthreads();
        if (ch + 2 < 8) loadT(V, (ch + 2) % 3, ch + 2);
        CP_COMMIT();
        const int buf = ch % 3;
        #pragma unroll
        for (int ks = 0; ks < 2; ks++) {
            uint32_t a[4];
            a[0] = packh2(acc[ch][2*ks  ][0], acc[ch][2*ks  ][1]);
            a[1] = packh2(acc[ch][2*ks  ][2], acc[ch][2*ks  ][3]);
            a[2] = packh2(acc[ch][2*ks+1][0], acc[ch][2*ks+1][1]);
            a[3] = packh2(acc[ch][2*ks+1][2], acc[ch][2*ks+1][3]);
            #pragma unroll
            for (int p = 0; p < 4; p++) {
                uint32_t mrr[4];
                ldmx4t(mrr, &KV[buf][wc * 32 + ks * 16 + lr16][p * 16 + lk8]);
                uint32_t b0[2] = {mrr[0], mrr[1]};
                uint32_t b1[2] = {mrr[2], mrr[3]};
                mma16816(oacc[2*p],   a, b0);
                mma16816(oacc[2*p+1], a, b1);
            }
        }
    }

    // ---- cross-warp reduction over wc and writeout -------------------------
    #pragma unroll
    for (int nb = 0; nb < 8; nb++) {
        int col = nb * 8 + lc2;
        *(float2*)&Po[(wc * 32 + R0) * 64 + col] = make_float2(oacc[nb][0], oacc[nb][1]);
        *(float2*)&Po[(wc * 32 + R1) * 64 + col] = make_float2(oacc[nb][2], oacc[nb][3]);
    }
    __syncthreads();
    {
        int row = t >> 3, c0 = (t & 7) * 8;
        float o[8];
        #pragma unroll
        for (int j = 0; j < 8; j++)
            o[j] = Po[row * 64 + c0 + j] + Po[(32 + row) * 64 + c0 + j]
                 + Po[(64 + row) * 64 + c0 + j] + Po[(96 + row) * 64 + c0 + j];
        __half* dst = ao + ((long)b * Ss + m0 + row) * Dd + h * 64 + c0;
        __align__(16) __half hh[8];
        #pragma unroll
        for (int j = 0; j < 8; j++) hh[j] = __float2half(o[j]);
        *(uint4*)dst = *(uint4*)hh;
    }
}

// ================= HMMA fp16 GEMM, 128x256 tile, 3-stage ====================
// C = A@B^T + bias (+res)(relu). A [M,K] row-major, B [N,K] row-major, fp16.
template<bool CONV, bool OUTH>
__global__ void __launch_bounds__(256, 1)
gemm256(const __half* __restrict__ A, int lda,
        const __half* __restrict__ B, int ldb,
        void* __restrict__ Cv, int ldc, int K,
        const float* __restrict__ bias,
        const float* __restrict__ res, int relu)
{
    extern __shared__ char dsm[];
    __half (*As)[128][40] = reinterpret_cast<__half(*)[128][40]>(dsm);
    __half (*Bs)[256][40] = reinterpret_cast<__half(*)[256][40]>(dsm + 3 * 128 * 40 * 2);

    const int t = threadIdx.x, lane = t & 31, w = t >> 5;
    const int wm = (w & 1) * 64;     // 2 warps along M
    const int wn = (w >> 1) * 64;    // 4 warps along N
    const int m0 = blockIdx.y * 128, n0 = blockIdx.x * 256;

    const int ar = t >> 1, ac = (t & 1) * 16;
    long abase = 0;
    const __half* agA = A;
    if (CONV) { int m = m0 + ar; abase = (long)((m >> 10) * SP + (m & 1023)); }
    else        agA = A + (long)(m0 + ar) * lda;

    const int br = t >> 1, bc = (t & 1) * 16;
    const __half* bg0 = B + (long)(n0 + br) * ldb;
    const __half* bg1 = B + (long)(n0 + br + 128) * ldb;

    float acc[4][8][4];
    #pragma unroll
    for (int i = 0; i < 4; i++)
        #pragma unroll
        for (int j = 0; j < 8; j++)
            #pragma unroll
            for (int p = 0; p < 4; p++) acc[i][j][p] = 0.f;

    const int KC = K >> 5;   // BK = 32

    auto loadbuf = [&](int buf, int k0) {
        if (CONV) {
            int kk = k0 + ac;
            int kc = kk >> 10, ci = kk & 1023;
            const __half* gp = A + (abase + kc) * (long)Dd + ci;
            cpa16(&As[buf][ar][ac],     gp);
            cpa16(&As[buf][ar][ac + 8], gp + 8);
        } else {
            const __half* gp = agA + k0 + ac;
            cpa16(&As[buf][ar][ac],     gp);
            cpa16(&As[buf][ar][ac + 8], gp + 8);
        }
        cpa16(&Bs[buf][br][bc],           bg0 + k0 + bc);
        cpa16(&Bs[buf][br][bc + 8],       bg0 + k0 + bc + 8);
        cpa16(&Bs[buf][br + 128][bc],     bg1 + k0 + bc);
        cpa16(&Bs[buf][br + 128][bc + 8], bg1 + k0 + bc + 8);
    };

    loadbuf(0, 0);  CP_COMMIT();
    loadbuf(1, 32); CP_COMMIT();

    const int lr16 = lane & 15;
    const int lk8  = (lane >> 4) * 8;

    for (int c = 0; c < KC; ++c) {
        CP_WAIT1();
        __syncthreads();
        if (c + 2 < KC) loadbuf((c + 2) % 3, (c + 2) * 32);
        CP_COMMIT();
        const int buf = c % 3;

        #pragma unroll
        for (int ks = 0; ks < 32; ks += 16) {
            uint32_t a[4][4];
            #pragma unroll
            for (int mf = 0; mf < 4; mf++)
                ldmx4(a[mf], &As[buf][wm + mf * 16 + lr16][ks + lk8]);
            uint32_t bf[8][2];
            #pragma unroll
            for (int p = 0; p < 4; p++) {
                uint32_t mrr[4];
                ldmx4(mrr, &Bs[buf][wn + p * 16 + lr16][ks + lk8]);
                bf[2*p][0]   = mrr[0]; bf[2*p][1]   = mrr[2];
                bf[2*p+1][0] = mrr[1]; bf[2*p+1][1] = mrr[3];
            }
            #pragma unroll
            for (int mf = 0; mf < 4; mf++)
                #pragma unroll
                for (int nf = 0; nf < 8; nf++)
                    mma16816(acc[mf][nf], a[mf], bf[nf]);
        }
    }

    // ---- epilogue ----
    const int lr = lane >> 2;
    const int lc = (lane & 3) * 2;
    #pragma unroll
    for (int mf = 0; mf < 4; mf++) {
        #pragma unroll
        for (int i = 0; i < 2; i++) {
            long mrow = m0 + wm + mf * 16 + lr + i * 8;
            #pragma unroll
            for (int nf = 0; nf < 8; nf++) {
                int col = n0 + wn + nf * 8 + lc;
                float v0 = acc[mf][nf][i * 2 + 0];
                float v1 = acc[mf][nf][i * 2 + 1];
                if (bias) { v0 += bias[col]; v1 += bias[col + 1]; }
                if (res) {
                    float2 rv = *(const float2*)(res + mrow * ldc + col);
                    v0 += rv.x; v1 += rv.y;
                }
                if (relu) { v0 = fmaxf(v0, 0.f); v1 = fmaxf(v1, 0.f); }
                if (OUTH) {
                    *(__half2*)((__half*)Cv + mrow * ldc + col) = __floats2half2_rn(v0, v1);
                } else {
                    *(float2*)((float*)Cv + mrow * ldc + col) = make_float2(v0, v1);
                }
            }
        }
    }
}

// ======================= prep kernels =======================================
struct P8 { const float* p[8]; };
__global__ void cast8(P8 s, __half* __restrict__ d)
{
    long i = ((long)blockIdx.x * 256 + threadIdx.x) * 8;   // over 8*2^20
    int slab = (int)(i >> 20);
    long off = i & 0xFFFFF;
    const float* sp = s.p[slab];
    float4 a = *(const float4*)(sp + off);
    float4 b = *(const float4*)(sp + off + 4);
    __align__(16) __half h[8] = {
        __float2half(a.x), __float2half(a.y), __float2half(a.z), __float2half(a.w),
        __float2half(b.x), __float2half(b.y), __float2half(b.z), __float2half(b.w)};
    *(uint4*)(d + i) = *(uint4*)h;
}

__global__ void cast16(const float* __restrict__ s, __half* __restrict__ d, long n)
{
    long i = ((long)blockIdx.x * 256 + threadIdx.x) * 8;
    if (i >= n) return;
    float4 a = *(const float4*)(s + i);
    float4 b = *(const float4*)(s + i + 4);
    __align__(16) __half h[8] = {
        __float2half(a.x), __float2half(a.y), __float2half(a.z), __float2half(a.w),
        __float2half(b.x), __float2half(b.y), __float2half(b.z), __float2half(b.w)};
    *(uint4*)(d + i) = *(uint4*)h;
}

__global__ void pad_cast(const float* __restrict__ x, __half* __restrict__ xp)
{
    long i = (long)blockIdx.x * 256 + threadIdx.x;   // over Bb*SP*Dd
    int c = (int)(i & 1023);
    long r = i >> 10;
    int b = (int)(r / SP);
    int s = (int)(r - (long)b * SP);
    float val = 0.f;
    if (s >= 4 && s < Ss + 4) val = x[((long)b * Ss + (s - 4)) * Dd + c];
    xp[i] = __float2half(val);
}

// conv1 weight repack via smem transpose: wp[n][kc][ci] = w[n][ci][kc]
__global__ void repack_t(const float* __restrict__ w, __half* __restrict__ wp)
{
    __shared__ float s[9216];
    long n = blockIdx.x;            // 0..DHh-1
    const float* src = w + n * 9216;
    for (int j = threadIdx.x; j < 9216; j += 256) s[j] = src[j];
    __syncthreads();
    __half* dst = wp + n * 9216;
    for (int j = threadIdx.x; j < 9216; j += 256) {
        int kc = j >> 10, ci = j & 1023;
        dst[j] = __float2half(s[ci * 9 + kc]);
    }
}

// merged bias vectors: bqkv = [bq1 | 0 | bv1], bkv = [0 | bv2]
__global__ void build_bias(const float* __restrict__ bq1, const float* __restrict__ bv1,
                           const float* __restrict__ bv2,
                           float* __restrict__ bqkv, float* __restrict__ bkv)
{
    int i = blockIdx.x * 256 + threadIdx.x;   // 0..5119
    if (i < 3072) {
        float v = 0.f;
        if (i < 1024) v = bq1[i];
        else if (i >= 2048) v = bv1[i - 2048];
        bqkv[i] = v;
    } else if (i < 5120) {
        int j = i - 3072;
        bkv[j] = (j < 1024) ? 0.f : bv2[j - 1024];
    }
}

// ======================= launcher ===========================================
extern "C" void kernel_launch(void* const* d_in, const int* in_sizes, int n_in,
                              void* d_out, int out_size)
{
    const float* x    = (const float*)d_in[0];
    const float* xa   = (const float*)d_in[1];
    const float* Wq1  = (const float*)d_in[2];
    const float* bq1  = (const float*)d_in[3];
    const float* Wk1  = (const float*)d_in[4];
    const float* Wv1  = (const float*)d_in[5];
    const float* bv1  = (const float*)d_in[6];
    const float* Wo1  = (const float*)d_in[7];
    const float* bo1  = (const float*)d_in[8];
    const float* gln1 = (const float*)d_in[9];
    const float* bln1 = (const float*)d_in[10];
    const float* Wq2  = (const float*)d_in[11];
    const float* bq2  = (const float*)d_in[12];
    const float* Wk2  = (const float*)d_in[13];
    const float* Wv2  = (const float*)d_in[14];
    const float* bv2  = (const float*)d_in[15];
    const float* Wo2  = (const float*)d_in[16];
    const float* bo2  = (const float*)d_in[17];
    const float* gln2 = (const float*)d_in[18];
    const float* bln2 = (const float*)d_in[19];
    const float* wc1  = (const float*)d_in[20];
    const float* bc1  = (const float*)d_in[21];
    const float* wc2  = (const float*)d_in[22];
    const float* bc2  = (const float*)d_in[23];
    const float* gln3 = (const float*)d_in[24];
    const float* bln3 = (const float*)d_in[25];

    __half *h16, *qkv16, *ao16, *xa16, *xp16, *y16, *wp16, *wc116, *wc216;
    float *px1, *px2, *pz, *pattn, *pbqkv, *pbkv;
    cudaGetSymbolAddress((void**)&h16,   g16_h);
    cudaGetSymbolAddress((void**)&qkv16, g16_qkv);
    cudaGetSymbolAddress((void**)&ao16,  g16_ao);
    cudaGetSymbolAddress((void**)&xa16,  g16_xa);
    cudaGetSymbolAddress((void**)&xp16,  g16_xpad);
    cudaGetSymbolAddress((void**)&y16,   g16_y);
    cudaGetSymbolAddress((void**)&wp16,  g16_wp);
    cudaGetSymbolAddress((void**)&wc116, g16_wc1);
    cudaGetSymbolAddress((void**)&wc216, g16_wc2);
    cudaGetSymbolAddress((void**)&px1,   g_x1);
    cudaGetSymbolAddress((void**)&px2,   g_x2);
    cudaGetSymbolAddress((void**)&pz,    g_z);
    cudaGetSymbolAddress((void**)&pattn, g_attn);
    cudaGetSymbolAddress((void**)&pbqkv, g_bqkv);
    cudaGetSymbolAddress((void**)&pbkv,  g_bkv);

    float* out = (float*)d_out;
    const size_t off1 = (size_t)Bb * Ss * Dd;
    const size_t asz  = (size_t)Bb * Hh * Ss * Tt;
    float* attn1 = pattn;
    float* attn2 = pattn;
    if ((size_t)out_size >= off1 + 2 * asz) {
        attn1 = out + off1;
        attn2 = out + off1 + asz;
    }

    // dynamic smem opt-in
    constexpr int SM256 = 3 * (128 * 40 + 256 * 40) * 2;    // 92160
    constexpr int SMQK  = 60416 + 32768;                    // 93184
    cudaFuncSetAttribute(gemm256<false,true >, cudaFuncAttributeMaxDynamicSharedMemorySize, SM256);
    cudaFuncSetAttribute(gemm256<false,false>, cudaFuncAttributeMaxDynamicSharedMemorySize, SM256);
    cudaFuncSetAttribute(gemm256<true ,true >, cudaFuncAttributeMaxDynamicSharedMemorySize, SM256);
    cudaFuncSetAttribute(qk_sm_av, cudaFuncAttributeMaxDynamicSharedMemorySize, SMQK);

    const long MM = (long)1024 * 1024;
    dim3 blk(256);
    dim3 gqkv(12, 32);           // N=3072, M=4096
    dim3 gq(4, 32);              // N=1024
    dim3 gkv(8, 32);             // N=2048
    dim3 go(4, 32);              // N=1024
    dim3 gqk(32, Bb * Hh);
    dim3 gc1(8, 32);             // N=2048
    dim3 gc2(4, 32);             // N=1024

    // ---- prep: weights, biases ----
    P8 ws; ws.p[0]=Wq1; ws.p[1]=Wk1; ws.p[2]=Wv1; ws.p[3]=Wo1;
           ws.p[4]=Wq2; ws.p[5]=Wk2; ws.p[6]=Wv2; ws.p[7]=Wo2;
    cast8<<<4096, 256>>>(ws, wp16);
    cast16<<<(int)(((long)Dd * DHh / 8 + 255) / 256), 256>>>(wc2, wc216, (long)Dd * DHh);
    cast16<<<(int)(((long)Bb * Tt * Dd / 8 + 255) / 256), 256>>>(xa, xa16, (long)Bb * Tt * Dd);
    repack_t<<<DHh, 256>>>(wc1, wc116);
    build_bias<<<20, 256>>>(bq1, bv1, bv2, pbqkv, pbkv);

    // ---- self attention ----
    ln_kernel<true><<<Bb * Ss, 256>>>(x, gln1, bln1, h16);
    gemm256<false,true><<<gqkv, blk, SM256>>>(h16, Dd, wp16, Dd,
        qkv16, 3072, Dd, pbqkv, nullptr, 0);
    qk_sm_av<<<gqk, blk, SMQK>>>(qkv16, attn1, ao16);
    gemm256<false,false><<<go, blk, SM256>>>(ao16, Dd, wp16 + 3 * MM, Dd,
        px1, Dd, Dd, bo1, x, 0);

    // ---- cross attention ----
    ln_kernel<true><<<Bb * Ss, 256>>>(px1, gln2, bln2, h16);
    gemm256<false,true><<<gq, blk, SM256>>>(h16, Dd, wp16 + 4 * MM, Dd,
        qkv16, 3072, Dd, bq2, nullptr, 0);
    gemm256<false,true><<<gkv, blk, SM256>>>(xa16, Dd, wp16 + 5 * MM, Dd,
        qkv16 + 1024, 3072, Dd, pbkv, nullptr, 0);
    qk_sm_av<<<gqk, blk, SMQK>>>(qkv16, attn2, ao16);
    gemm256<false,false><<<go, blk, SM256>>>(ao16, Dd, wp16 + 7 * MM, Dd,
        px2, Dd, Dd, bo2, px1, 0);

    // ---- conv FFN ----
    pad_cast<<<(Bb * SP * Dd) / 256, 256>>>(px2, xp16);
    gemm256<true,true><<<gc1, blk, SM256>>>(xp16, Dd, wc116, 9216,
        y16, DHh, 9216, bc1, nullptr, 1);
    gemm256<false,false><<<gc2, blk, SM256>>>(y16, DHh, wc216, DHh,
        pz, Dd, DHh, bc2, px2, 0);
    ln_kernel<false><<<Bb * Ss, 256>>>(pz, gln3, bln3, out);
}